// round 1
// baseline (speedup 1.0000x reference)
#include <cuda_runtime.h>
#include <cuda_bf16.h>
#include <math.h>

// Problem constants
#define N_ENT 100000
#define N_REL 1000
#define RANK  256
#define TWO_R 512
#define BATCH 1024
#define MAX_NB 50

// Output layout (flattened tuple): scores, n_lhs, n_rel, n_rhs, n_gec
#define OFF_SCORES 0
#define OFF_NLHS   ((size_t)BATCH * N_ENT)                    // 102,400,000
#define OFF_NREL   (OFF_NLHS + (size_t)BATCH * RANK)
#define OFF_NRHS   (OFF_NREL + (size_t)BATCH * RANK)
#define OFF_NGEC   (OFF_NRHS + (size_t)BATCH * RANK)

// Scratch (static device globals; no allocation allowed)
__device__ float g_w0 [BATCH * RANK];
__device__ float g_w1 [BATCH * RANK];
__device__ float g_ec0[BATCH * RANK];
__device__ float g_ec1[BATCH * RANK];
__device__ float g_en0[BATCH * RANK];
__device__ float g_en1[BATCH * RANK];
__device__ float g_Q  [BATCH * TWO_R];   // [q_re | q_im] per row

// ---------------------------------------------------------------------------
// K1: w0/w1 = t0@W0 - t1@W1 + bw0 ; t0@W1 + t1@W0 + bw1
// 8 batch rows per block (amortize W0/W1 traffic), 256 threads (one per k)
// ---------------------------------------------------------------------------
#define K1_ROWS 8
__global__ __launch_bounds__(256) void k1_wproj(
    const int* __restrict__ x,
    const float* __restrict__ E_ent, const float* __restrict__ E_rel,
    const float* __restrict__ W0, const float* __restrict__ W1,
    const float* __restrict__ bw0, const float* __restrict__ bw1)
{
    __shared__ float t0s[K1_ROWS][TWO_R];
    __shared__ float t1s[K1_ROWS][TWO_R];
    const int b0 = blockIdx.x * K1_ROWS;
    const int tid = threadIdx.x;

    for (int rr = 0; rr < K1_ROWS; rr++) {
        const int b = b0 + rr;
        const size_t lhs = (size_t)x[b * 3 + 0];
        const size_t rel = (size_t)x[b * 3 + 1];
        const float* lrow = E_ent + lhs * TWO_R;
        const float* rrow = E_rel + rel * TWO_R;
        for (int j = tid; j < TWO_R; j += 256) {
            // t0 = [l0 | r0], t1 = [l1 | r1]
            if (j < RANK) {
                t0s[rr][j] = lrow[j];
                t1s[rr][j] = lrow[RANK + j];
            } else {
                t0s[rr][j] = rrow[j - RANK];
                t1s[rr][j] = rrow[RANK + (j - RANK)];
            }
        }
    }
    __syncthreads();

    const int k = tid;
    float a0[K1_ROWS], a1[K1_ROWS];
#pragma unroll
    for (int rr = 0; rr < K1_ROWS; rr++) { a0[rr] = 0.f; a1[rr] = 0.f; }

    for (int j = 0; j < TWO_R; j++) {
        const float w0jk = W0[j * RANK + k];
        const float w1jk = W1[j * RANK + k];
#pragma unroll
        for (int rr = 0; rr < K1_ROWS; rr++) {
            const float a = t0s[rr][j];
            const float c = t1s[rr][j];
            a0[rr] += a * w0jk - c * w1jk;
            a1[rr] += a * w1jk + c * w0jk;
        }
    }
    const float b0k = bw0[k], b1k = bw1[k];
#pragma unroll
    for (int rr = 0; rr < K1_ROWS; rr++) {
        g_w0[(b0 + rr) * RANK + k] = a0[rr] + b0k;
        g_w1[(b0 + rr) * RANK + k] = a1[rr] + b1k;
    }
}

// ---------------------------------------------------------------------------
// K2: logits over 50 neighbors, softmax, ec0/ec1 weighted sums.
// One block per batch row, 256 threads (8 warps). Warp w handles neighbors
// w, w+8, ... for the logit dots; then thread-per-k pass for ec.
// ---------------------------------------------------------------------------
__global__ __launch_bounds__(256) void k2_attn(
    const int* __restrict__ nb_idx, const float* __restrict__ E_ent)
{
    __shared__ float w0s[RANK], w1s[RANK];
    __shared__ float logit_s[MAX_NB];
    __shared__ float alpha_s[MAX_NB];
    __shared__ int   idx_s[MAX_NB];

    const int b = blockIdx.x;
    const int tid = threadIdx.x;
    const int wid = tid >> 5;
    const int lane = tid & 31;

    w0s[tid] = g_w0[b * RANK + tid];
    w1s[tid] = g_w1[b * RANK + tid];
    if (tid < MAX_NB) idx_s[tid] = nb_idx[b * MAX_NB + tid];
    __syncthreads();

    for (int m = wid; m < MAX_NB; m += 8) {
        const float* row = E_ent + (size_t)idx_s[m] * TWO_R;
        float s = 0.f;
#pragma unroll
        for (int k = lane; k < RANK; k += 32)
            s += w0s[k] * row[k] - w1s[k] * row[RANK + k];
#pragma unroll
        for (int o = 16; o > 0; o >>= 1) s += __shfl_xor_sync(0xffffffffu, s, o);
        if (lane == 0) logit_s[m] = s;
    }
    __syncthreads();

    if (tid == 0) {  // tiny serial softmax over 50
        float mx = logit_s[0];
        for (int m = 1; m < MAX_NB; m++) mx = fmaxf(mx, logit_s[m]);
        float sum = 0.f;
        for (int m = 0; m < MAX_NB; m++) { float e = __expf(logit_s[m] - mx); alpha_s[m] = e; sum += e; }
        const float inv = 1.0f / sum;
        for (int m = 0; m < MAX_NB; m++) alpha_s[m] *= inv;
    }
    __syncthreads();

    const int k = tid;
    float acc0 = 0.f, acc1 = 0.f;
#pragma unroll 5
    for (int m = 0; m < MAX_NB; m++) {
        const float* row = E_ent + (size_t)idx_s[m] * TWO_R;
        const float a = alpha_s[m];
        acc0 += a * row[k];
        acc1 += a * row[RANK + k];
    }
    g_ec0[b * RANK + k] = acc0;
    g_ec1[b * RANK + k] = acc1;
}

// ---------------------------------------------------------------------------
// K3a: ec0n/ec1n complex projection by W20/W21, 8 rows/block
// ---------------------------------------------------------------------------
#define K3_ROWS 8
__global__ __launch_bounds__(256) void k3a_ecproj(
    const float* __restrict__ W20, const float* __restrict__ W21,
    const float* __restrict__ bw20, const float* __restrict__ bw21)
{
    __shared__ float e0s[K3_ROWS][RANK];
    __shared__ float e1s[K3_ROWS][RANK];
    const int b0 = blockIdx.x * K3_ROWS;
    const int tid = threadIdx.x;

    for (int rr = 0; rr < K3_ROWS; rr++) {
        e0s[rr][tid] = g_ec0[(b0 + rr) * RANK + tid];
        e1s[rr][tid] = g_ec1[(b0 + rr) * RANK + tid];
    }
    __syncthreads();

    const int k = tid;
    float a0[K3_ROWS], a1[K3_ROWS];
#pragma unroll
    for (int rr = 0; rr < K3_ROWS; rr++) { a0[rr] = 0.f; a1[rr] = 0.f; }

    for (int j = 0; j < RANK; j++) {
        const float w20 = W20[j * RANK + k];
        const float w21 = W21[j * RANK + k];
#pragma unroll
        for (int rr = 0; rr < K3_ROWS; rr++) {
            const float a = e0s[rr][j];
            const float c = e1s[rr][j];
            a0[rr] += a * w20 - c * w21;
            a1[rr] += a * w21 + c * w20;
        }
    }
    const float b20 = bw20[k], b21 = bw21[k];
#pragma unroll
    for (int rr = 0; rr < K3_ROWS; rr++) {
        g_en0[(b0 + rr) * RANK + k] = a0[rr] + b20;
        g_en1[(b0 + rr) * RANK + k] = a1[rr] + b21;
    }
}

// ---------------------------------------------------------------------------
// K3b: gate scalar, gec, q_re/q_im into Q, plus the four norm outputs
// One block per batch row, 256 threads (thread = k)
// ---------------------------------------------------------------------------
__global__ __launch_bounds__(256) void k3b_gate_q(
    const int* __restrict__ x,
    const float* __restrict__ E_ent, const float* __restrict__ E_rel,
    const float* __restrict__ Uo0, const float* __restrict__ Uo1,
    const float* __restrict__ Wo0, const float* __restrict__ b_g,
    float* __restrict__ out)
{
    __shared__ float warp_part[8];
    __shared__ float g_sh;
    const int b = blockIdx.x;
    const int k = threadIdx.x;
    const int wid = k >> 5, lane = k & 31;

    const size_t lhs = (size_t)x[b * 3 + 0];
    const size_t rel = (size_t)x[b * 3 + 1];
    const size_t rhs = (size_t)x[b * 3 + 2];

    const float l0 = E_ent[lhs * TWO_R + k];
    const float l1 = E_ent[lhs * TWO_R + RANK + k];
    const float r0 = E_rel[rel * TWO_R + k];
    const float r1 = E_rel[rel * TWO_R + RANK + k];
    const float o0 = E_ent[rhs * TWO_R + k];
    const float o1 = E_ent[rhs * TWO_R + RANK + k];

    const float en0 = g_en0[b * RANK + k];
    const float en1 = g_en1[b * RANK + k];

    const float sr = l0 * r0 - l1 * r1;     // srrr - siri
    const float si = l1 * r0 + l0 * r1;     // sirr + srri

    float p = sr * Uo0[k] - si * Uo1[k] + en0 * Wo0[k];
#pragma unroll
    for (int o = 16; o > 0; o >>= 1) p += __shfl_xor_sync(0xffffffffu, p, o);
    if (lane == 0) warp_part[wid] = p;
    __syncthreads();
    if (k == 0) {
        float tot = 0.f;
#pragma unroll
        for (int w = 0; w < 8; w++) tot += warp_part[w];
        tot += b_g[0];
        g_sh = 1.0f / (1.0f + __expf(-tot));
    }
    __syncthreads();
    const float g = g_sh;

    const float gec0 = g * en0 + (1.0f - g);
    const float gec1 = g * en1;

    const float q_re = sr * gec0 + si * gec1;
    const float q_im = si * gec0 - sr * gec1;

    g_Q[b * TWO_R + k]        = q_re;
    g_Q[b * TWO_R + RANK + k] = q_im;

    const size_t nk = (size_t)b * RANK + k;
    out[OFF_NLHS + nk] = sqrtf(l0 * l0 + l1 * l1);
    out[OFF_NREL + nk] = sqrtf(r0 * r0 + r1 * r1);
    out[OFF_NRHS + nk] = sqrtf(o0 * o0 + o1 * o1);
    out[OFF_NGEC + nk] = sqrtf(gec0 * gec0 + gec1 * gec1);
}

// ---------------------------------------------------------------------------
// K4: scores = Q (1024x512) @ E_ent^T (512x100000). Tiled fp32 SGEMM.
// 128x128 block tile, BK=16, 256 threads, 8x8 register tile per thread.
// ---------------------------------------------------------------------------
#define BM 128
#define BN 128
#define BK 16
#define TM 8
#define TN 8

__global__ __launch_bounds__(256, 2) void k4_scores(
    const float* __restrict__ Q, const float* __restrict__ E,
    float* __restrict__ C)
{
    __shared__ float As[BK][BM];
    __shared__ float Bs[BK][BN];

    const int tid = threadIdx.x;
    const int tx = tid & 15;        // 0..15 -> n
    const int ty = tid >> 4;        // 0..15 -> m
    const int m0 = blockIdx.y * BM;
    const int n0 = blockIdx.x * BN;

    const int lrow  = tid >> 2;          // 0..63
    const int lcol4 = (tid & 3) * 4;     // 0,4,8,12

    float acc[TM][TN];
#pragma unroll
    for (int i = 0; i < TM; i++)
#pragma unroll
        for (int j = 0; j < TN; j++) acc[i][j] = 0.f;

    for (int k0 = 0; k0 < TWO_R; k0 += BK) {
#pragma unroll
        for (int h = 0; h < 2; h++) {
            const int r = lrow + h * 64;
            const float4 v = *(const float4*)(Q + (size_t)(m0 + r) * TWO_R + k0 + lcol4);
            As[lcol4 + 0][r] = v.x; As[lcol4 + 1][r] = v.y;
            As[lcol4 + 2][r] = v.z; As[lcol4 + 3][r] = v.w;
        }
#pragma unroll
        for (int h = 0; h < 2; h++) {
            const int r = lrow + h * 64;
            const int e = n0 + r;
            float4 v = make_float4(0.f, 0.f, 0.f, 0.f);
            if (e < N_ENT) v = *(const float4*)(E + (size_t)e * TWO_R + k0 + lcol4);
            Bs[lcol4 + 0][r] = v.x; Bs[lcol4 + 1][r] = v.y;
            Bs[lcol4 + 2][r] = v.z; Bs[lcol4 + 3][r] = v.w;
        }
        __syncthreads();

#pragma unroll
        for (int kk = 0; kk < BK; kk++) {
            float ra[TM], rb[TN];
#pragma unroll
            for (int i = 0; i < TM; i++) ra[i] = As[kk][ty * TM + i];
#pragma unroll
            for (int j = 0; j < TN; j++) rb[j] = Bs[kk][tx * TN + j];
#pragma unroll
            for (int i = 0; i < TM; i++)
#pragma unroll
                for (int j = 0; j < TN; j++) acc[i][j] += ra[i] * rb[j];
        }
        __syncthreads();
    }

#pragma unroll
    for (int i = 0; i < TM; i++) {
        const int m = m0 + ty * TM + i;
        float* crow = C + (size_t)m * N_ENT;
#pragma unroll
        for (int j4 = 0; j4 < TN; j4 += 4) {
            const int n = n0 + tx * TN + j4;
            if (n + 3 < N_ENT) {
                float4 v;
                v.x = acc[i][j4 + 0]; v.y = acc[i][j4 + 1];
                v.z = acc[i][j4 + 2]; v.w = acc[i][j4 + 3];
                *(float4*)(crow + n) = v;
            } else {
#pragma unroll
                for (int j = 0; j < 4; j++)
                    if (n + j < N_ENT) crow[n + j] = acc[i][j4 + j];
            }
        }
    }
}

// ---------------------------------------------------------------------------
extern "C" void kernel_launch(void* const* d_in, const int* in_sizes, int n_in,
                              void* d_out, int out_size)
{
    const int*   x      = (const int*)  d_in[0];
    const int*   nb_idx = (const int*)  d_in[1];
    const float* E_ent  = (const float*)d_in[2];
    const float* E_rel  = (const float*)d_in[3];
    const float* W0     = (const float*)d_in[4];
    const float* W1     = (const float*)d_in[5];
    const float* bw0    = (const float*)d_in[6];
    const float* bw1    = (const float*)d_in[7];
    const float* W20    = (const float*)d_in[8];
    const float* W21    = (const float*)d_in[9];
    const float* bw20   = (const float*)d_in[10];
    const float* bw21   = (const float*)d_in[11];
    const float* Uo0    = (const float*)d_in[12];
    const float* Uo1    = (const float*)d_in[13];
    const float* Wo0    = (const float*)d_in[14];
    const float* b_g    = (const float*)d_in[15];
    float* out = (float*)d_out;

    float* Qp;   cudaGetSymbolAddress((void**)&Qp, g_Q);

    k1_wproj<<<BATCH / K1_ROWS, 256>>>(x, E_ent, E_rel, W0, W1, bw0, bw1);
    k2_attn <<<BATCH, 256>>>(nb_idx, E_ent);
    k3a_ecproj<<<BATCH / K3_ROWS, 256>>>(W20, W21, bw20, bw21);
    k3b_gate_q<<<BATCH, 256>>>(x, E_ent, E_rel, Uo0, Uo1, Wo0, b_g, out);

    dim3 grid4((N_ENT + BN - 1) / BN, BATCH / BM);
    k4_scores<<<grid4, 256>>>(Qp, E_ent, out + OFF_SCORES);
}

// round 3
// speedup vs baseline: 2.7443x; 2.7443x over previous
#include <cuda_runtime.h>
#include <cuda_bf16.h>
#include <cstdint>
#include <math.h>

// Problem constants
#define N_ENT 100000
#define N_REL 1000
#define RANK  256
#define TWO_R 512
#define BATCH 1024
#define MAX_NB 50

// Output layout (flattened tuple): scores, n_lhs, n_rel, n_rhs, n_gec
#define OFF_SCORES 0
#define OFF_NLHS   ((size_t)BATCH * N_ENT)
#define OFF_NREL   (OFF_NLHS + (size_t)BATCH * RANK)
#define OFF_NRHS   (OFF_NREL + (size_t)BATCH * RANK)
#define OFF_NGEC   (OFF_NRHS + (size_t)BATCH * RANK)

// Scratch (static device globals; no allocation allowed)
__device__ float g_w0 [BATCH * RANK];
__device__ float g_w1 [BATCH * RANK];
__device__ float g_ec0[BATCH * RANK];
__device__ float g_ec1[BATCH * RANK];
__device__ float g_en0[BATCH * RANK];
__device__ float g_en1[BATCH * RANK];

// split-bf16 operands for the big GEMM
__device__ __nv_bfloat16 g_Qh[BATCH * TWO_R];
__device__ __nv_bfloat16 g_Ql[BATCH * TWO_R];
__device__ __nv_bfloat16 g_Eh[(size_t)N_ENT * TWO_R];
__device__ __nv_bfloat16 g_El[(size_t)N_ENT * TWO_R];

// ===========================================================================
// PTX helpers (compute_103-safe subset: cp.async / ldmatrix / mma.sync only)
// ===========================================================================
__device__ __forceinline__ uint32_t smem_to_u32(const void* smem_ptr) {
    uint32_t addr;
    asm("{ .reg .u64 tmp; cvta.to.shared.u64 tmp, %1; cvt.u32.u64 %0, tmp; }"
        : "=r"(addr) : "l"(smem_ptr));
    return addr;
}

#define CP_ASYNC16(smem_u32, gptr) \
    asm volatile("cp.async.cg.shared.global [%0], [%1], 16;" \
        :: "r"(smem_u32), "l"(gptr) : "memory")

#define CP_ASYNC_COMMIT() \
    asm volatile("cp.async.commit_group;" ::: "memory")

#define CP_ASYNC_WAIT_GROUP(n) \
    asm volatile("cp.async.wait_group %0;" :: "n"(n) : "memory")

__device__ __forceinline__ void ldsm_x4(uint32_t r[4], uint32_t addr) {
    asm volatile("ldmatrix.sync.aligned.m8n8.x4.shared.b16 {%0,%1,%2,%3}, [%4];"
        : "=r"(r[0]), "=r"(r[1]), "=r"(r[2]), "=r"(r[3]) : "r"(addr));
}

__device__ __forceinline__ void mma_16816(
    float c[4], const uint32_t a[4], uint32_t b0, uint32_t b1)
{
    asm volatile(
        "mma.sync.aligned.m16n8k16.row.col.f32.bf16.bf16.f32 "
        "{%0,%1,%2,%3}, {%4,%5,%6,%7}, {%8,%9}, {%0,%1,%2,%3};"
        : "+f"(c[0]), "+f"(c[1]), "+f"(c[2]), "+f"(c[3])
        : "r"(a[0]), "r"(a[1]), "r"(a[2]), "r"(a[3]), "r"(b0), "r"(b1));
}

// ---------------------------------------------------------------------------
// K0: split E_ent (fp32) into bf16 hi/lo
// ---------------------------------------------------------------------------
__global__ __launch_bounds__(256) void k0_splitE(const float* __restrict__ E)
{
    const size_t i = ((size_t)blockIdx.x * 256 + threadIdx.x) * 4;
    const float4 v = *(const float4*)(E + i);
    const __nv_bfloat16 h0 = __float2bfloat16(v.x);
    const __nv_bfloat16 h1 = __float2bfloat16(v.y);
    const __nv_bfloat16 h2 = __float2bfloat16(v.z);
    const __nv_bfloat16 h3 = __float2bfloat16(v.w);
    const __nv_bfloat16 l0 = __float2bfloat16(v.x - __bfloat162float(h0));
    const __nv_bfloat16 l1 = __float2bfloat16(v.y - __bfloat162float(h1));
    const __nv_bfloat16 l2 = __float2bfloat16(v.z - __bfloat162float(h2));
    const __nv_bfloat16 l3 = __float2bfloat16(v.w - __bfloat162float(h3));
    __nv_bfloat162* ph = (__nv_bfloat162*)(g_Eh + i);
    __nv_bfloat162* pl = (__nv_bfloat162*)(g_El + i);
    ph[0] = __halves2bfloat162(h0, h1);
    ph[1] = __halves2bfloat162(h2, h3);
    pl[0] = __halves2bfloat162(l0, l1);
    pl[1] = __halves2bfloat162(l2, l3);
}

// ---------------------------------------------------------------------------
// K1: w0/w1 = t0@W0 - t1@W1 + bw0 ; t0@W1 + t1@W0 + bw1
// ---------------------------------------------------------------------------
#define K1_ROWS 8
__global__ __launch_bounds__(256) void k1_wproj(
    const int* __restrict__ x,
    const float* __restrict__ E_ent, const float* __restrict__ E_rel,
    const float* __restrict__ W0, const float* __restrict__ W1,
    const float* __restrict__ bw0, const float* __restrict__ bw1)
{
    __shared__ float t0s[K1_ROWS][TWO_R];
    __shared__ float t1s[K1_ROWS][TWO_R];
    const int b0 = blockIdx.x * K1_ROWS;
    const int tid = threadIdx.x;

    for (int rr = 0; rr < K1_ROWS; rr++) {
        const int b = b0 + rr;
        const size_t lhs = (size_t)x[b * 3 + 0];
        const size_t rel = (size_t)x[b * 3 + 1];
        const float* lrow = E_ent + lhs * TWO_R;
        const float* rrow = E_rel + rel * TWO_R;
        for (int j = tid; j < TWO_R; j += 256) {
            if (j < RANK) {
                t0s[rr][j] = lrow[j];
                t1s[rr][j] = lrow[RANK + j];
            } else {
                t0s[rr][j] = rrow[j - RANK];
                t1s[rr][j] = rrow[RANK + (j - RANK)];
            }
        }
    }
    __syncthreads();

    const int k = tid;
    float a0[K1_ROWS], a1[K1_ROWS];
#pragma unroll
    for (int rr = 0; rr < K1_ROWS; rr++) { a0[rr] = 0.f; a1[rr] = 0.f; }

    for (int j = 0; j < TWO_R; j++) {
        const float w0jk = W0[j * RANK + k];
        const float w1jk = W1[j * RANK + k];
#pragma unroll
        for (int rr = 0; rr < K1_ROWS; rr++) {
            const float a = t0s[rr][j];
            const float c = t1s[rr][j];
            a0[rr] += a * w0jk - c * w1jk;
            a1[rr] += a * w1jk + c * w0jk;
        }
    }
    const float b0k = bw0[k], b1k = bw1[k];
#pragma unroll
    for (int rr = 0; rr < K1_ROWS; rr++) {
        g_w0[(b0 + rr) * RANK + k] = a0[rr] + b0k;
        g_w1[(b0 + rr) * RANK + k] = a1[rr] + b1k;
    }
}

// ---------------------------------------------------------------------------
// K2: logits over 50 neighbors, softmax, ec0/ec1 weighted sums.
// ---------------------------------------------------------------------------
__global__ __launch_bounds__(256) void k2_attn(
    const int* __restrict__ nb_idx, const float* __restrict__ E_ent)
{
    __shared__ float w0s[RANK], w1s[RANK];
    __shared__ float logit_s[MAX_NB];
    __shared__ float alpha_s[MAX_NB];
    __shared__ int   idx_s[MAX_NB];

    const int b = blockIdx.x;
    const int tid = threadIdx.x;
    const int wid = tid >> 5;
    const int lane = tid & 31;

    w0s[tid] = g_w0[b * RANK + tid];
    w1s[tid] = g_w1[b * RANK + tid];
    if (tid < MAX_NB) idx_s[tid] = nb_idx[b * MAX_NB + tid];
    __syncthreads();

    for (int m = wid; m < MAX_NB; m += 8) {
        const float* row = E_ent + (size_t)idx_s[m] * TWO_R;
        float s = 0.f;
#pragma unroll
        for (int k = lane; k < RANK; k += 32)
            s += w0s[k] * row[k] - w1s[k] * row[RANK + k];
#pragma unroll
        for (int o = 16; o > 0; o >>= 1) s += __shfl_xor_sync(0xffffffffu, s, o);
        if (lane == 0) logit_s[m] = s;
    }
    __syncthreads();

    if (tid == 0) {
        float mx = logit_s[0];
        for (int m = 1; m < MAX_NB; m++) mx = fmaxf(mx, logit_s[m]);
        float sum = 0.f;
        for (int m = 0; m < MAX_NB; m++) { float e = __expf(logit_s[m] - mx); alpha_s[m] = e; sum += e; }
        const float inv = 1.0f / sum;
        for (int m = 0; m < MAX_NB; m++) alpha_s[m] *= inv;
    }
    __syncthreads();

    const int k = tid;
    float acc0 = 0.f, acc1 = 0.f;
#pragma unroll 5
    for (int m = 0; m < MAX_NB; m++) {
        const float* row = E_ent + (size_t)idx_s[m] * TWO_R;
        const float a = alpha_s[m];
        acc0 += a * row[k];
        acc1 += a * row[RANK + k];
    }
    g_ec0[b * RANK + k] = acc0;
    g_ec1[b * RANK + k] = acc1;
}

// ---------------------------------------------------------------------------
// K3a: ec0n/ec1n complex projection by W20/W21, 8 rows/block
// ---------------------------------------------------------------------------
#define K3_ROWS 8
__global__ __launch_bounds__(256) void k3a_ecproj(
    const float* __restrict__ W20, const float* __restrict__ W21,
    const float* __restrict__ bw20, const float* __restrict__ bw21)
{
    __shared__ float e0s[K3_ROWS][RANK];
    __shared__ float e1s[K3_ROWS][RANK];
    const int b0 = blockIdx.x * K3_ROWS;
    const int tid = threadIdx.x;

    for (int rr = 0; rr < K3_ROWS; rr++) {
        e0s[rr][tid] = g_ec0[(b0 + rr) * RANK + tid];
        e1s[rr][tid] = g_ec1[(b0 + rr) * RANK + tid];
    }
    __syncthreads();

    const int k = tid;
    float a0[K3_ROWS], a1[K3_ROWS];
#pragma unroll
    for (int rr = 0; rr < K3_ROWS; rr++) { a0[rr] = 0.f; a1[rr] = 0.f; }

    for (int j = 0; j < RANK; j++) {
        const float w20 = W20[j * RANK + k];
        const float w21 = W21[j * RANK + k];
#pragma unroll
        for (int rr = 0; rr < K3_ROWS; rr++) {
            const float a = e0s[rr][j];
            const float c = e1s[rr][j];
            a0[rr] += a * w20 - c * w21;
            a1[rr] += a * w21 + c * w20;
        }
    }
    const float b20 = bw20[k], b21 = bw21[k];
#pragma unroll
    for (int rr = 0; rr < K3_ROWS; rr++) {
        g_en0[(b0 + rr) * RANK + k] = a0[rr] + b20;
        g_en1[(b0 + rr) * RANK + k] = a1[rr] + b21;
    }
}

// ---------------------------------------------------------------------------
// K3b: gate scalar, gec, q_re/q_im (split bf16 into g_Qh/g_Ql), norms
// ---------------------------------------------------------------------------
__global__ __launch_bounds__(256) void k3b_gate_q(
    const int* __restrict__ x,
    const float* __restrict__ E_ent, const float* __restrict__ E_rel,
    const float* __restrict__ Uo0, const float* __restrict__ Uo1,
    const float* __restrict__ Wo0, const float* __restrict__ b_g,
    float* __restrict__ out)
{
    __shared__ float warp_part[8];
    __shared__ float g_sh;
    const int b = blockIdx.x;
    const int k = threadIdx.x;
    const int wid = k >> 5, lane = k & 31;

    const size_t lhs = (size_t)x[b * 3 + 0];
    const size_t rel = (size_t)x[b * 3 + 1];
    const size_t rhs = (size_t)x[b * 3 + 2];

    const float l0 = E_ent[lhs * TWO_R + k];
    const float l1 = E_ent[lhs * TWO_R + RANK + k];
    const float r0 = E_rel[rel * TWO_R + k];
    const float r1 = E_rel[rel * TWO_R + RANK + k];
    const float o0 = E_ent[rhs * TWO_R + k];
    const float o1 = E_ent[rhs * TWO_R + RANK + k];

    const float en0 = g_en0[b * RANK + k];
    const float en1 = g_en1[b * RANK + k];

    const float sr = l0 * r0 - l1 * r1;
    const float si = l1 * r0 + l0 * r1;

    float p = sr * Uo0[k] - si * Uo1[k] + en0 * Wo0[k];
#pragma unroll
    for (int o = 16; o > 0; o >>= 1) p += __shfl_xor_sync(0xffffffffu, p, o);
    if (lane == 0) warp_part[wid] = p;
    __syncthreads();
    if (k == 0) {
        float tot = 0.f;
#pragma unroll
        for (int w = 0; w < 8; w++) tot += warp_part[w];
        tot += b_g[0];
        g_sh = 1.0f / (1.0f + __expf(-tot));
    }
    __syncthreads();
    const float g = g_sh;

    const float gec0 = g * en0 + (1.0f - g);
    const float gec1 = g * en1;

    const float q_re = sr * gec0 + si * gec1;
    const float q_im = si * gec0 - sr * gec1;

    const __nv_bfloat16 qrh = __float2bfloat16(q_re);
    const __nv_bfloat16 qih = __float2bfloat16(q_im);
    g_Qh[b * TWO_R + k]        = qrh;
    g_Qh[b * TWO_R + RANK + k] = qih;
    g_Ql[b * TWO_R + k]        = __float2bfloat16(q_re - __bfloat162float(qrh));
    g_Ql[b * TWO_R + RANK + k] = __float2bfloat16(q_im - __bfloat162float(qih));

    const size_t nk = (size_t)b * RANK + k;
    out[OFF_NLHS + nk] = sqrtf(l0 * l0 + l1 * l1);
    out[OFF_NREL + nk] = sqrtf(r0 * r0 + r1 * r1);
    out[OFF_NRHS + nk] = sqrtf(o0 * o0 + o1 * o1);
    out[OFF_NGEC + nk] = sqrtf(gec0 * gec0 + gec1 * gec1);
}

// ---------------------------------------------------------------------------
// K4: scores = Q (1024x512) @ E^T (512x100000), split-bf16 (3 products) on
// mma.sync.m16n8k16 (HMMA). CTA 128x128, 8 warps (2x4), warp tile 64x32,
// K chunk 32, 4-stage cp.async pipeline. Rows padded to 80B: conflict-free
// ldmatrix without XOR swizzle.
// ---------------------------------------------------------------------------
#define NCHUNK 16
#define ROW_B   80                  // padded row bytes (64B data + 16B pad)
#define TILE_B  (128 * ROW_B)       // 10240
#define STAGE_B (4 * TILE_B)        // Ah, Al, Bh, Bl = 40960
#define NSTAGE  4
#define SMEM_K4 (NSTAGE * STAGE_B)  // 163840

__device__ __forceinline__ void k4_load_chunk(
    uint32_t sb, int chunk, int m0, int n0,
    const __nv_bfloat16* Qh, const __nv_bfloat16* Ql,
    const __nv_bfloat16* Eh, const __nv_bfloat16* El, int tid)
{
    const int k0 = chunk * 32;
#pragma unroll
    for (int u = 0; u < 2; u++) {
        const int idx = tid + u * 256;       // 0..511
        const int row = idx >> 2;            // 0..127
        const int g   = idx & 3;             // 16B group
        const uint32_t soff = (uint32_t)(row * ROW_B + g * 16);
        const size_t kcol = (size_t)(k0 + g * 8);
        const size_t arow = (size_t)(m0 + row) * TWO_R + kcol;
        int er = n0 + row; if (er >= N_ENT) er = N_ENT - 1;
        const size_t brow = (size_t)er * TWO_R + kcol;
        CP_ASYNC16(sb + 0 * TILE_B + soff, Qh + arow);
        CP_ASYNC16(sb + 1 * TILE_B + soff, Ql + arow);
        CP_ASYNC16(sb + 2 * TILE_B + soff, Eh + brow);
        CP_ASYNC16(sb + 3 * TILE_B + soff, El + brow);
    }
}

__global__ __launch_bounds__(256) void k4_hmma(
    const __nv_bfloat16* __restrict__ Qh, const __nv_bfloat16* __restrict__ Ql,
    const __nv_bfloat16* __restrict__ Eh, const __nv_bfloat16* __restrict__ El,
    float* __restrict__ C)
{
    extern __shared__ __align__(1024) char smem[];
    const uint32_t sbase = smem_to_u32(smem);
    const int tid  = threadIdx.x;
    const int wid  = tid >> 5;
    const int lane = tid & 31;
    const int wm   = wid & 1;       // 0..1  -> 64-row slice
    const int wn   = wid >> 1;      // 0..3  -> 32-col slice
    const int m0   = blockIdx.x * 128;   // M fast dim: co-resident CTAs share B
    const int n0   = blockIdx.y * 128;

    // ldmatrix lane decomposition (same for A and B tiles)
    const int laneRow = ((lane >> 3) & 1) * 8 + (lane & 7);  // row within 16
    const int laneG   = lane >> 4;                           // k 16B-group sel
    const int rowAbase = wm * 64 + laneRow;
    const int rowBbase = wn * 32 + laneRow;

    float acc[4][4][4];
#pragma unroll
    for (int a = 0; a < 4; a++)
#pragma unroll
        for (int b = 0; b < 4; b++)
#pragma unroll
            for (int c = 0; c < 4; c++) acc[a][b][c] = 0.f;

    // prologue: fill 3 stages
    k4_load_chunk(sbase + 0 * STAGE_B, 0, m0, n0, Qh, Ql, Eh, El, tid);
    CP_ASYNC_COMMIT();
    k4_load_chunk(sbase + 1 * STAGE_B, 1, m0, n0, Qh, Ql, Eh, El, tid);
    CP_ASYNC_COMMIT();
    k4_load_chunk(sbase + 2 * STAGE_B, 2, m0, n0, Qh, Ql, Eh, El, tid);
    CP_ASYNC_COMMIT();

#pragma unroll 1
    for (int i = 0; i < NCHUNK; i++) {
        CP_ASYNC_WAIT_GROUP(2);
        __syncthreads();

        if (i + 3 < NCHUNK)
            k4_load_chunk(sbase + ((i + 3) & 3) * STAGE_B, i + 3, m0, n0,
                          Qh, Ql, Eh, El, tid);
        CP_ASYNC_COMMIT();

        const uint32_t sb  = sbase + (i & 3) * STAGE_B;
        const uint32_t sAh = sb;
        const uint32_t sAl = sb + TILE_B;
        const uint32_t sBh = sb + 2 * TILE_B;
        const uint32_t sBl = sb + 3 * TILE_B;

#pragma unroll
        for (int kh = 0; kh < 2; kh++) {
            const uint32_t gof = (uint32_t)((2 * kh + laneG) * 16);

            uint32_t ah[4][4], bh[2][4];
#pragma unroll
            for (int mt = 0; mt < 4; mt++)
                ldsm_x4(ah[mt], sAh + (uint32_t)((rowAbase + mt * 16) * ROW_B) + gof);
#pragma unroll
            for (int q = 0; q < 2; q++)
                ldsm_x4(bh[q], sBh + (uint32_t)((rowBbase + q * 16) * ROW_B) + gof);

            // Ah * Bh
#pragma unroll
            for (int mt = 0; mt < 4; mt++)
#pragma unroll
                for (int j = 0; j < 4; j++)
                    mma_16816(acc[mt][j], ah[mt], bh[j >> 1][j & 1], bh[j >> 1][2 + (j & 1)]);

            // Ah * Bl
            {
                uint32_t bl[2][4];
#pragma unroll
                for (int q = 0; q < 2; q++)
                    ldsm_x4(bl[q], sBl + (uint32_t)((rowBbase + q * 16) * ROW_B) + gof);
#pragma unroll
                for (int mt = 0; mt < 4; mt++)
#pragma unroll
                    for (int j = 0; j < 4; j++)
                        mma_16816(acc[mt][j], ah[mt], bl[j >> 1][j & 1], bl[j >> 1][2 + (j & 1)]);
            }

            // Al * Bh
            {
                uint32_t al[4][4];
#pragma unroll
                for (int mt = 0; mt < 4; mt++)
                    ldsm_x4(al[mt], sAl + (uint32_t)((rowAbase + mt * 16) * ROW_B) + gof);
#pragma unroll
                for (int mt = 0; mt < 4; mt++)
#pragma unroll
                    for (int j = 0; j < 4; j++)
                        mma_16816(acc[mt][j], al[mt], bh[j >> 1][j & 1], bh[j >> 1][2 + (j & 1)]);
            }
        }
    }

    // Epilogue: C frag (m16n8): thread t -> rows t/4, t/4+8; cols 2*(t%4)+{0,1}
    const int erow = (lane >> 2);
    const int ecol = (lane & 3) * 2;
#pragma unroll
    for (int mt = 0; mt < 4; mt++) {
        const int r1 = m0 + wm * 64 + mt * 16 + erow;
#pragma unroll
        for (int j = 0; j < 4; j++) {
            const int n = n0 + wn * 32 + j * 8 + ecol;
            if (n < N_ENT) {
                float2 v01 = make_float2(acc[mt][j][0], acc[mt][j][1]);
                float2 v23 = make_float2(acc[mt][j][2], acc[mt][j][3]);
                *(float2*)(C + (size_t)r1 * N_ENT + n) = v01;
                *(float2*)(C + (size_t)(r1 + 8) * N_ENT + n) = v23;
            }
        }
    }
}

// ---------------------------------------------------------------------------
extern "C" void kernel_launch(void* const* d_in, const int* in_sizes, int n_in,
                              void* d_out, int out_size)
{
    const int*   x      = (const int*)  d_in[0];
    const int*   nb_idx = (const int*)  d_in[1];
    const float* E_ent  = (const float*)d_in[2];
    const float* E_rel  = (const float*)d_in[3];
    const float* W0     = (const float*)d_in[4];
    const float* W1     = (const float*)d_in[5];
    const float* bw0    = (const float*)d_in[6];
    const float* bw1    = (const float*)d_in[7];
    const float* W20    = (const float*)d_in[8];
    const float* W21    = (const float*)d_in[9];
    const float* bw20   = (const float*)d_in[10];
    const float* bw21   = (const float*)d_in[11];
    const float* Uo0    = (const float*)d_in[12];
    const float* Uo1    = (const float*)d_in[13];
    const float* Wo0    = (const float*)d_in[14];
    const float* b_g    = (const float*)d_in[15];
    float* out = (float*)d_out;

    __nv_bfloat16 *Qh, *Ql, *Eh, *El;
    cudaGetSymbolAddress((void**)&Qh, g_Qh);
    cudaGetSymbolAddress((void**)&Ql, g_Ql);
    cudaGetSymbolAddress((void**)&Eh, g_Eh);
    cudaGetSymbolAddress((void**)&El, g_El);

    cudaFuncSetAttribute(k4_hmma, cudaFuncAttributeMaxDynamicSharedMemorySize, SMEM_K4);

    // E split: 51.2M elements / (256 threads * 4 per thread) = 50000 blocks
    k0_splitE<<<50000, 256>>>(E_ent);

    k1_wproj<<<BATCH / K1_ROWS, 256>>>(x, E_ent, E_rel, W0, W1, bw0, bw1);
    k2_attn <<<BATCH, 256>>>(nb_idx, E_ent);
    k3a_ecproj<<<BATCH / K3_ROWS, 256>>>(W20, W21, bw20, bw21);
    k3b_gate_q<<<BATCH, 256>>>(x, E_ent, E_rel, Uo0, Uo1, Wo0, b_g, out);

    dim3 g4(BATCH / 128, (N_ENT + 127) / 128);   // (8, 782), M fast
    k4_hmma<<<g4, 256, SMEM_K4>>>(Qh, Ql, Eh, El, out + OFF_SCORES);
}

// round 4
// speedup vs baseline: 3.4683x; 1.2638x over previous
#include <cuda_runtime.h>
#include <cuda_bf16.h>
#include <cstdint>
#include <math.h>

// Problem constants
#define N_ENT 100000
#define N_REL 1000
#define RANK  256
#define TWO_R 512
#define BATCH 1024
#define MAX_NB 50

// Output layout (flattened tuple): scores, n_lhs, n_rel, n_rhs, n_gec
#define OFF_SCORES 0
#define OFF_NLHS   ((size_t)BATCH * N_ENT)
#define OFF_NREL   (OFF_NLHS + (size_t)BATCH * RANK)
#define OFF_NRHS   (OFF_NREL + (size_t)BATCH * RANK)
#define OFF_NGEC   (OFF_NRHS + (size_t)BATCH * RANK)

// Scratch (static device globals; no allocation allowed)
__device__ float g_w0 [BATCH * RANK];
__device__ float g_w1 [BATCH * RANK];
__device__ float g_ec0[BATCH * RANK];
__device__ float g_ec1[BATCH * RANK];
__device__ float g_en0[BATCH * RANK];
__device__ float g_en1[BATCH * RANK];

// split-bf16 operands for the big GEMM
__device__ __nv_bfloat16 g_Qh[BATCH * TWO_R];
__device__ __nv_bfloat16 g_Ql[BATCH * TWO_R];
__device__ __nv_bfloat16 g_Eh[(size_t)N_ENT * TWO_R];
__device__ __nv_bfloat16 g_El[(size_t)N_ENT * TWO_R];

// ===========================================================================
// PTX helpers (compute_103-safe subset: cp.async / ldmatrix / mma.sync only)
// ===========================================================================
__device__ __forceinline__ uint32_t smem_to_u32(const void* smem_ptr) {
    uint32_t addr;
    asm("{ .reg .u64 tmp; cvta.to.shared.u64 tmp, %1; cvt.u32.u64 %0, tmp; }"
        : "=r"(addr) : "l"(smem_ptr));
    return addr;
}

#define CP_ASYNC16(smem_u32, gptr) \
    asm volatile("cp.async.cg.shared.global [%0], [%1], 16;" \
        :: "r"(smem_u32), "l"(gptr) : "memory")

#define CP_ASYNC_COMMIT() \
    asm volatile("cp.async.commit_group;" ::: "memory")

#define CP_ASYNC_WAIT_GROUP(n) \
    asm volatile("cp.async.wait_group %0;" :: "n"(n) : "memory")

__device__ __forceinline__ void ldsm_x4(uint32_t r[4], uint32_t addr) {
    asm volatile("ldmatrix.sync.aligned.m8n8.x4.shared.b16 {%0,%1,%2,%3}, [%4];"
        : "=r"(r[0]), "=r"(r[1]), "=r"(r[2]), "=r"(r[3]) : "r"(addr));
}

__device__ __forceinline__ void mma_16816(
    float c[4], const uint32_t a[4], uint32_t b0, uint32_t b1)
{
    asm volatile(
        "mma.sync.aligned.m16n8k16.row.col.f32.bf16.bf16.f32 "
        "{%0,%1,%2,%3}, {%4,%5,%6,%7}, {%8,%9}, {%0,%1,%2,%3};"
        : "+f"(c[0]), "+f"(c[1]), "+f"(c[2]), "+f"(c[3])
        : "r"(a[0]), "r"(a[1]), "r"(a[2]), "r"(a[3]), "r"(b0), "r"(b1));
}

// ---------------------------------------------------------------------------
// K0: split E_ent (fp32) into bf16 hi/lo
// ---------------------------------------------------------------------------
__global__ __launch_bounds__(256) void k0_splitE(const float* __restrict__ E)
{
    const size_t i = ((size_t)blockIdx.x * 256 + threadIdx.x) * 4;
    const float4 v = *(const float4*)(E + i);
    const __nv_bfloat16 h0 = __float2bfloat16(v.x);
    const __nv_bfloat16 h1 = __float2bfloat16(v.y);
    const __nv_bfloat16 h2 = __float2bfloat16(v.z);
    const __nv_bfloat16 h3 = __float2bfloat16(v.w);
    const __nv_bfloat16 l0 = __float2bfloat16(v.x - __bfloat162float(h0));
    const __nv_bfloat16 l1 = __float2bfloat16(v.y - __bfloat162float(h1));
    const __nv_bfloat16 l2 = __float2bfloat16(v.z - __bfloat162float(h2));
    const __nv_bfloat16 l3 = __float2bfloat16(v.w - __bfloat162float(h3));
    __nv_bfloat162* ph = (__nv_bfloat162*)(g_Eh + i);
    __nv_bfloat162* pl = (__nv_bfloat162*)(g_El + i);
    ph[0] = __halves2bfloat162(h0, h1);
    ph[1] = __halves2bfloat162(h2, h3);
    pl[0] = __halves2bfloat162(l0, l1);
    pl[1] = __halves2bfloat162(l2, l3);
}

// ---------------------------------------------------------------------------
// K1: w0/w1 = t0@W0 - t1@W1 + bw0 ; t0@W1 + t1@W0 + bw1
// 4 rows/block -> 256 blocks (>=1.7 CTA/SM), unrolled j loop for MLP
// ---------------------------------------------------------------------------
#define K1_ROWS 4
__global__ __launch_bounds__(256) void k1_wproj(
    const int* __restrict__ x,
    const float* __restrict__ E_ent, const float* __restrict__ E_rel,
    const float* __restrict__ W0, const float* __restrict__ W1,
    const float* __restrict__ bw0, const float* __restrict__ bw1)
{
    __shared__ float t0s[K1_ROWS][TWO_R];
    __shared__ float t1s[K1_ROWS][TWO_R];
    const int b0 = blockIdx.x * K1_ROWS;
    const int tid = threadIdx.x;

    for (int rr = 0; rr < K1_ROWS; rr++) {
        const int b = b0 + rr;
        const size_t lhs = (size_t)x[b * 3 + 0];
        const size_t rel = (size_t)x[b * 3 + 1];
        const float* lrow = E_ent + lhs * TWO_R;
        const float* rrow = E_rel + rel * TWO_R;
        for (int j = tid; j < TWO_R; j += 256) {
            if (j < RANK) {
                t0s[rr][j] = lrow[j];
                t1s[rr][j] = lrow[RANK + j];
            } else {
                t0s[rr][j] = rrow[j - RANK];
                t1s[rr][j] = rrow[RANK + (j - RANK)];
            }
        }
    }
    __syncthreads();

    const int k = tid;
    float a0[K1_ROWS], a1[K1_ROWS];
#pragma unroll
    for (int rr = 0; rr < K1_ROWS; rr++) { a0[rr] = 0.f; a1[rr] = 0.f; }

#pragma unroll 8
    for (int j = 0; j < TWO_R; j++) {
        const float w0jk = W0[j * RANK + k];
        const float w1jk = W1[j * RANK + k];
#pragma unroll
        for (int rr = 0; rr < K1_ROWS; rr++) {
            const float a = t0s[rr][j];
            const float c = t1s[rr][j];
            a0[rr] += a * w0jk - c * w1jk;
            a1[rr] += a * w1jk + c * w0jk;
        }
    }
    const float b0k = bw0[k], b1k = bw1[k];
#pragma unroll
    for (int rr = 0; rr < K1_ROWS; rr++) {
        g_w0[(b0 + rr) * RANK + k] = a0[rr] + b0k;
        g_w1[(b0 + rr) * RANK + k] = a1[rr] + b1k;
    }
}

// ---------------------------------------------------------------------------
// K2: logits over 50 neighbors, softmax, ec0/ec1 weighted sums.
// Neighbor rows staged once into dynamic smem (100 KB) via cp.async.
// ---------------------------------------------------------------------------
#define K2_SMEM (MAX_NB * TWO_R * 4)   // 102400
__global__ __launch_bounds__(256) void k2_attn(
    const int* __restrict__ nb_idx, const float* __restrict__ E_ent)
{
    extern __shared__ __align__(16) float nbs[];   // [MAX_NB][TWO_R]
    __shared__ float w0s[RANK], w1s[RANK];
    __shared__ float logit_s[MAX_NB];
    __shared__ float alpha_s[MAX_NB];
    __shared__ int   idx_s[MAX_NB];

    const int b = blockIdx.x;
    const int tid = threadIdx.x;
    const int wid = tid >> 5;
    const int lane = tid & 31;

    w0s[tid] = g_w0[b * RANK + tid];
    w1s[tid] = g_w1[b * RANK + tid];
    if (tid < MAX_NB) idx_s[tid] = nb_idx[b * MAX_NB + tid];
    __syncthreads();

    // stage all 50 rows into smem: 50 * 128 float4 transfers
    const uint32_t nbs_u = smem_to_u32(nbs);
    for (int u = tid; u < MAX_NB * 128; u += 256) {
        const int m = u >> 7;
        const int q = u & 127;
        CP_ASYNC16(nbs_u + (uint32_t)u * 16,
                   E_ent + (size_t)idx_s[m] * TWO_R + q * 4);
    }
    CP_ASYNC_COMMIT();
    CP_ASYNC_WAIT_GROUP(0);
    __syncthreads();

    for (int m = wid; m < MAX_NB; m += 8) {
        const float* row = nbs + m * TWO_R;
        float s = 0.f;
#pragma unroll
        for (int k = lane; k < RANK; k += 32)
            s += w0s[k] * row[k] - w1s[k] * row[RANK + k];
#pragma unroll
        for (int o = 16; o > 0; o >>= 1) s += __shfl_xor_sync(0xffffffffu, s, o);
        if (lane == 0) logit_s[m] = s;
    }
    __syncthreads();

    if (tid == 0) {
        float mx = logit_s[0];
        for (int m = 1; m < MAX_NB; m++) mx = fmaxf(mx, logit_s[m]);
        float sum = 0.f;
        for (int m = 0; m < MAX_NB; m++) { float e = __expf(logit_s[m] - mx); alpha_s[m] = e; sum += e; }
        const float inv = 1.0f / sum;
        for (int m = 0; m < MAX_NB; m++) alpha_s[m] *= inv;
    }
    __syncthreads();

    const int k = tid;
    float acc0 = 0.f, acc1 = 0.f;
#pragma unroll 10
    for (int m = 0; m < MAX_NB; m++) {
        const float a = alpha_s[m];
        acc0 += a * nbs[m * TWO_R + k];
        acc1 += a * nbs[m * TWO_R + RANK + k];
    }
    g_ec0[b * RANK + k] = acc0;
    g_ec1[b * RANK + k] = acc1;
}

// ---------------------------------------------------------------------------
// K3a: ec0n/ec1n complex projection by W20/W21, 4 rows/block -> 256 blocks
// ---------------------------------------------------------------------------
#define K3_ROWS 4
__global__ __launch_bounds__(256) void k3a_ecproj(
    const float* __restrict__ W20, const float* __restrict__ W21,
    const float* __restrict__ bw20, const float* __restrict__ bw21)
{
    __shared__ float e0s[K3_ROWS][RANK];
    __shared__ float e1s[K3_ROWS][RANK];
    const int b0 = blockIdx.x * K3_ROWS;
    const int tid = threadIdx.x;

    for (int rr = 0; rr < K3_ROWS; rr++) {
        e0s[rr][tid] = g_ec0[(b0 + rr) * RANK + tid];
        e1s[rr][tid] = g_ec1[(b0 + rr) * RANK + tid];
    }
    __syncthreads();

    const int k = tid;
    float a0[K3_ROWS], a1[K3_ROWS];
#pragma unroll
    for (int rr = 0; rr < K3_ROWS; rr++) { a0[rr] = 0.f; a1[rr] = 0.f; }

#pragma unroll 8
    for (int j = 0; j < RANK; j++) {
        const float w20 = W20[j * RANK + k];
        const float w21 = W21[j * RANK + k];
#pragma unroll
        for (int rr = 0; rr < K3_ROWS; rr++) {
            const float a = e0s[rr][j];
            const float c = e1s[rr][j];
            a0[rr] += a * w20 - c * w21;
            a1[rr] += a * w21 + c * w20;
        }
    }
    const float b20 = bw20[k], b21 = bw21[k];
#pragma unroll
    for (int rr = 0; rr < K3_ROWS; rr++) {
        g_en0[(b0 + rr) * RANK + k] = a0[rr] + b20;
        g_en1[(b0 + rr) * RANK + k] = a1[rr] + b21;
    }
}

// ---------------------------------------------------------------------------
// K3b: gate scalar, gec, q_re/q_im (split bf16 into g_Qh/g_Ql), norms
// ---------------------------------------------------------------------------
__global__ __launch_bounds__(256) void k3b_gate_q(
    const int* __restrict__ x,
    const float* __restrict__ E_ent, const float* __restrict__ E_rel,
    const float* __restrict__ Uo0, const float* __restrict__ Uo1,
    const float* __restrict__ Wo0, const float* __restrict__ b_g,
    float* __restrict__ out)
{
    __shared__ float warp_part[8];
    __shared__ float g_sh;
    const int b = blockIdx.x;
    const int k = threadIdx.x;
    const int wid = k >> 5, lane = k & 31;

    const size_t lhs = (size_t)x[b * 3 + 0];
    const size_t rel = (size_t)x[b * 3 + 1];
    const size_t rhs = (size_t)x[b * 3 + 2];

    const float l0 = E_ent[lhs * TWO_R + k];
    const float l1 = E_ent[lhs * TWO_R + RANK + k];
    const float r0 = E_rel[rel * TWO_R + k];
    const float r1 = E_rel[rel * TWO_R + RANK + k];
    const float o0 = E_ent[rhs * TWO_R + k];
    const float o1 = E_ent[rhs * TWO_R + RANK + k];

    const float en0 = g_en0[b * RANK + k];
    const float en1 = g_en1[b * RANK + k];

    const float sr = l0 * r0 - l1 * r1;
    const float si = l1 * r0 + l0 * r1;

    float p = sr * Uo0[k] - si * Uo1[k] + en0 * Wo0[k];
#pragma unroll
    for (int o = 16; o > 0; o >>= 1) p += __shfl_xor_sync(0xffffffffu, p, o);
    if (lane == 0) warp_part[wid] = p;
    __syncthreads();
    if (k == 0) {
        float tot = 0.f;
#pragma unroll
        for (int w = 0; w < 8; w++) tot += warp_part[w];
        tot += b_g[0];
        g_sh = 1.0f / (1.0f + __expf(-tot));
    }
    __syncthreads();
    const float g = g_sh;

    const float gec0 = g * en0 + (1.0f - g);
    const float gec1 = g * en1;

    const float q_re = sr * gec0 + si * gec1;
    const float q_im = si * gec0 - sr * gec1;

    const __nv_bfloat16 qrh = __float2bfloat16(q_re);
    const __nv_bfloat16 qih = __float2bfloat16(q_im);
    g_Qh[b * TWO_R + k]        = qrh;
    g_Qh[b * TWO_R + RANK + k] = qih;
    g_Ql[b * TWO_R + k]        = __float2bfloat16(q_re - __bfloat162float(qrh));
    g_Ql[b * TWO_R + RANK + k] = __float2bfloat16(q_im - __bfloat162float(qih));

    const size_t nk = (size_t)b * RANK + k;
    out[OFF_NLHS + nk] = sqrtf(l0 * l0 + l1 * l1);
    out[OFF_NREL + nk] = sqrtf(r0 * r0 + r1 * r1);
    out[OFF_NRHS + nk] = sqrtf(o0 * o0 + o1 * o1);
    out[OFF_NGEC + nk] = sqrtf(gec0 * gec0 + gec1 * gec1);
}

// ---------------------------------------------------------------------------
// K4: scores = Q (1024x512) @ E^T (512x100000), split-bf16 (3 products) on
// mma.sync.m16n8k16. CTA tile 128x256, 8 warps (2x4), warp tile 64x64,
// K chunk 32, 3-stage cp.async pipeline. mma:ldsm = 6:1 (tensor-bound).
// ---------------------------------------------------------------------------
#define NCHUNK 16
#define ROW_B    80                    // padded row bytes (64B data + 16B pad)
#define A_TILE_B (128 * ROW_B)         // 10240
#define B_TILE_B (256 * ROW_B)         // 20480
#define STAGE_B  (2 * A_TILE_B + 2 * B_TILE_B)   // 61440
#define NSTAGE   3
#define SMEM_K4  (NSTAGE * STAGE_B)    // 184320

__device__ __forceinline__ void k4_load_chunk(
    uint32_t sb, int chunk, int m0, int n0,
    const __nv_bfloat16* Qh, const __nv_bfloat16* Ql,
    const __nv_bfloat16* Eh, const __nv_bfloat16* El, int tid)
{
    const int k0 = chunk * 32;
    // A tiles (Ah, Al): 1024 x 16B transfers
#pragma unroll
    for (int u = 0; u < 4; u++) {
        const int idx = tid + u * 256;        // 0..1023
        const int t   = idx >> 9;             // 0=Ah, 1=Al
        const int rem = idx & 511;
        const int row = rem >> 2;
        const int g   = rem & 3;
        const uint32_t soff = sb + (uint32_t)(t * A_TILE_B + row * ROW_B + g * 16);
        const size_t goff = (size_t)(m0 + row) * TWO_R + k0 + g * 8;
        CP_ASYNC16(soff, (t ? Ql : Qh) + goff);
    }
    // B tiles (Bh, Bl): 2048 x 16B transfers
#pragma unroll
    for (int u = 0; u < 8; u++) {
        const int idx = tid + u * 256;        // 0..2047
        const int t   = idx >> 10;            // 0=Bh, 1=Bl
        const int rem = idx & 1023;
        const int row = rem >> 2;
        const int g   = rem & 3;
        int er = n0 + row; if (er >= N_ENT) er = N_ENT - 1;
        const uint32_t soff = sb + (uint32_t)(2 * A_TILE_B + t * B_TILE_B + row * ROW_B + g * 16);
        const size_t goff = (size_t)er * TWO_R + k0 + g * 8;
        CP_ASYNC16(soff, (t ? El : Eh) + goff);
    }
}

__global__ __launch_bounds__(256) void k4_hmma(
    const __nv_bfloat16* __restrict__ Qh, const __nv_bfloat16* __restrict__ Ql,
    const __nv_bfloat16* __restrict__ Eh, const __nv_bfloat16* __restrict__ El,
    float* __restrict__ C)
{
    extern __shared__ __align__(1024) char smem[];
    const uint32_t sbase = smem_to_u32(smem);
    const int tid  = threadIdx.x;
    const int wid  = tid >> 5;
    const int lane = tid & 31;
    const int wm   = wid & 1;       // 0..1 -> 64-row slice
    const int wn   = wid >> 1;      // 0..3 -> 64-col slice
    const int m0   = blockIdx.x * 128;   // M fast dim: co-resident CTAs share B
    const int n0   = blockIdx.y * 256;

    const int laneRow = ((lane >> 3) & 1) * 8 + (lane & 7);
    const int laneG   = lane >> 4;
    const int rowAbase = wm * 64 + laneRow;
    const int rowBbase = wn * 64 + laneRow;

    float acc[4][8][4];
#pragma unroll
    for (int a = 0; a < 4; a++)
#pragma unroll
        for (int b = 0; b < 8; b++)
#pragma unroll
            for (int c = 0; c < 4; c++) acc[a][b][c] = 0.f;

    // prologue: fill 2 stages
    k4_load_chunk(sbase + 0 * STAGE_B, 0, m0, n0, Qh, Ql, Eh, El, tid);
    CP_ASYNC_COMMIT();
    k4_load_chunk(sbase + 1 * STAGE_B, 1, m0, n0, Qh, Ql, Eh, El, tid);
    CP_ASYNC_COMMIT();

    int stg = 0;
#pragma unroll 1
    for (int i = 0; i < NCHUNK; i++) {
        CP_ASYNC_WAIT_GROUP(1);
        __syncthreads();

        // refill the stage freed in iteration i-1
        if (i + 2 < NCHUNK) {
            int ns = stg + 2; if (ns >= NSTAGE) ns -= NSTAGE;
            k4_load_chunk(sbase + ns * STAGE_B, i + 2, m0, n0, Qh, Ql, Eh, El, tid);
        }
        CP_ASYNC_COMMIT();

        const uint32_t sb  = sbase + stg * STAGE_B;
        const uint32_t sAh = sb;
        const uint32_t sAl = sb + A_TILE_B;
        const uint32_t sBh = sb + 2 * A_TILE_B;
        const uint32_t sBl = sb + 2 * A_TILE_B + B_TILE_B;

#pragma unroll
        for (int kh = 0; kh < 2; kh++) {
            const uint32_t gof = (uint32_t)((2 * kh + laneG) * 16);

            uint32_t ah[4][4], bh[4][4];
#pragma unroll
            for (int mt = 0; mt < 4; mt++)
                ldsm_x4(ah[mt], sAh + (uint32_t)((rowAbase + mt * 16) * ROW_B) + gof);
#pragma unroll
            for (int q = 0; q < 4; q++)
                ldsm_x4(bh[q], sBh + (uint32_t)((rowBbase + q * 16) * ROW_B) + gof);

            // Ah * Bh
#pragma unroll
            for (int mt = 0; mt < 4; mt++)
#pragma unroll
                for (int j = 0; j < 8; j++)
                    mma_16816(acc[mt][j], ah[mt], bh[j >> 1][j & 1], bh[j >> 1][2 + (j & 1)]);

            // Ah * Bl
            {
                uint32_t bl[4][4];
#pragma unroll
                for (int q = 0; q < 4; q++)
                    ldsm_x4(bl[q], sBl + (uint32_t)((rowBbase + q * 16) * ROW_B) + gof);
#pragma unroll
                for (int mt = 0; mt < 4; mt++)
#pragma unroll
                    for (int j = 0; j < 8; j++)
                        mma_16816(acc[mt][j], ah[mt], bl[j >> 1][j & 1], bl[j >> 1][2 + (j & 1)]);
            }

            // Al * Bh
            {
                uint32_t al[4][4];
#pragma unroll
                for (int mt = 0; mt < 4; mt++)
                    ldsm_x4(al[mt], sAl + (uint32_t)((rowAbase + mt * 16) * ROW_B) + gof);
#pragma unroll
                for (int mt = 0; mt < 4; mt++)
#pragma unroll
                    for (int j = 0; j < 8; j++)
                        mma_16816(acc[mt][j], al[mt], bh[j >> 1][j & 1], bh[j >> 1][2 + (j & 1)]);
            }
        }

        stg = stg + 1; if (stg >= NSTAGE) stg = 0;
    }

    // Epilogue: C frag (m16n8): thread t -> rows t/4, t/4+8; cols 2*(t%4)+{0,1}
    const int erow = (lane >> 2);
    const int ecol = (lane & 3) * 2;
#pragma unroll
    for (int mt = 0; mt < 4; mt++) {
        const int r1 = m0 + wm * 64 + mt * 16 + erow;
#pragma unroll
        for (int j = 0; j < 8; j++) {
            const int n = n0 + wn * 64 + j * 8 + ecol;
            if (n < N_ENT) {
                float2 v01 = make_float2(acc[mt][j][0], acc[mt][j][1]);
                float2 v23 = make_float2(acc[mt][j][2], acc[mt][j][3]);
                *(float2*)(C + (size_t)r1 * N_ENT + n) = v01;
                *(float2*)(C + (size_t)(r1 + 8) * N_ENT + n) = v23;
            }
        }
    }
}

// ---------------------------------------------------------------------------
extern "C" void kernel_launch(void* const* d_in, const int* in_sizes, int n_in,
                              void* d_out, int out_size)
{
    const int*   x      = (const int*)  d_in[0];
    const int*   nb_idx = (const int*)  d_in[1];
    const float* E_ent  = (const float*)d_in[2];
    const float* E_rel  = (const float*)d_in[3];
    const float* W0     = (const float*)d_in[4];
    const float* W1     = (const float*)d_in[5];
    const float* bw0    = (const float*)d_in[6];
    const float* bw1    = (const float*)d_in[7];
    const float* W20    = (const float*)d_in[8];
    const float* W21    = (const float*)d_in[9];
    const float* bw20   = (const float*)d_in[10];
    const float* bw21   = (const float*)d_in[11];
    const float* Uo0    = (const float*)d_in[12];
    const float* Uo1    = (const float*)d_in[13];
    const float* Wo0    = (const float*)d_in[14];
    const float* b_g    = (const float*)d_in[15];
    float* out = (float*)d_out;

    __nv_bfloat16 *Qh, *Ql, *Eh, *El;
    cudaGetSymbolAddress((void**)&Qh, g_Qh);
    cudaGetSymbolAddress((void**)&Ql, g_Ql);
    cudaGetSymbolAddress((void**)&Eh, g_Eh);
    cudaGetSymbolAddress((void**)&El, g_El);

    cudaFuncSetAttribute(k4_hmma, cudaFuncAttributeMaxDynamicSharedMemorySize, SMEM_K4);
    cudaFuncSetAttribute(k2_attn, cudaFuncAttributeMaxDynamicSharedMemorySize, K2_SMEM);

    k0_splitE<<<50000, 256>>>(E_ent);

    k1_wproj<<<BATCH / K1_ROWS, 256>>>(x, E_ent, E_rel, W0, W1, bw0, bw1);
    k2_attn <<<BATCH, 256, K2_SMEM>>>(nb_idx, E_ent);
    k3a_ecproj<<<BATCH / K3_ROWS, 256>>>(W20, W21, bw20, bw21);
    k3b_gate_q<<<BATCH, 256>>>(x, E_ent, E_rel, Uo0, Uo1, Wo0, b_g, out);

    dim3 g4(BATCH / 128, (N_ENT + 255) / 256);   // (8, 391), M fast
    k4_hmma<<<g4, 256, SMEM_K4>>>(Qh, Ql, Eh, El, out + OFF_SCORES);
}

// round 5
// speedup vs baseline: 3.5049x; 1.0105x over previous
#include <cuda_runtime.h>
#include <cuda_bf16.h>
#include <cstdint>
#include <math.h>

// Problem constants
#define N_ENT 100000
#define N_REL 1000
#define RANK  256
#define TWO_R 512
#define BATCH 1024
#define MAX_NB 50

// Output layout (flattened tuple): scores, n_lhs, n_rel, n_rhs, n_gec
#define OFF_SCORES 0
#define OFF_NLHS   ((size_t)BATCH * N_ENT)
#define OFF_NREL   (OFF_NLHS + (size_t)BATCH * RANK)
#define OFF_NRHS   (OFF_NREL + (size_t)BATCH * RANK)
#define OFF_NGEC   (OFF_NRHS + (size_t)BATCH * RANK)

// Scratch (static device globals; no allocation allowed)
__device__ float g_w0 [BATCH * RANK];
__device__ float g_w1 [BATCH * RANK];
__device__ float g_ec0[BATCH * RANK];
__device__ float g_ec1[BATCH * RANK];
__device__ float g_en0[BATCH * RANK];
__device__ float g_en1[BATCH * RANK];

// split-bf16 operands for the big GEMM
__device__ __nv_bfloat16 g_Qh[BATCH * TWO_R];
__device__ __nv_bfloat16 g_Ql[BATCH * TWO_R];
__device__ __nv_bfloat16 g_Eh[(size_t)N_ENT * TWO_R];
__device__ __nv_bfloat16 g_El[(size_t)N_ENT * TWO_R];

// ===========================================================================
// PTX helpers (compute_103-safe subset: cp.async / ldmatrix / mma.sync only)
// ===========================================================================
__device__ __forceinline__ uint32_t smem_to_u32(const void* smem_ptr) {
    uint32_t addr;
    asm("{ .reg .u64 tmp; cvta.to.shared.u64 tmp, %1; cvt.u32.u64 %0, tmp; }"
        : "=r"(addr) : "l"(smem_ptr));
    return addr;
}

#define CP_ASYNC16(smem_u32, gptr) \
    asm volatile("cp.async.cg.shared.global [%0], [%1], 16;" \
        :: "r"(smem_u32), "l"(gptr) : "memory")

#define CP_ASYNC_COMMIT() \
    asm volatile("cp.async.commit_group;" ::: "memory")

#define CP_ASYNC_WAIT_GROUP(n) \
    asm volatile("cp.async.wait_group %0;" :: "n"(n) : "memory")

__device__ __forceinline__ void ldsm_x4(uint32_t r[4], uint32_t addr) {
    asm volatile("ldmatrix.sync.aligned.m8n8.x4.shared.b16 {%0,%1,%2,%3}, [%4];"
        : "=r"(r[0]), "=r"(r[1]), "=r"(r[2]), "=r"(r[3]) : "r"(addr));
}

__device__ __forceinline__ void mma_16816(
    float c[4], const uint32_t a[4], uint32_t b0, uint32_t b1)
{
    asm volatile(
        "mma.sync.aligned.m16n8k16.row.col.f32.bf16.bf16.f32 "
        "{%0,%1,%2,%3}, {%4,%5,%6,%7}, {%8,%9}, {%0,%1,%2,%3};"
        : "+f"(c[0]), "+f"(c[1]), "+f"(c[2]), "+f"(c[3])
        : "r"(a[0]), "r"(a[1]), "r"(a[2]), "r"(a[3]), "r"(b0), "r"(b1));
}

// ---------------------------------------------------------------------------
// K0: split E_ent (fp32) into bf16 hi/lo
// ---------------------------------------------------------------------------
__global__ __launch_bounds__(256) void k0_splitE(const float* __restrict__ E)
{
    const size_t i = ((size_t)blockIdx.x * 256 + threadIdx.x) * 4;
    const float4 v = *(const float4*)(E + i);
    const __nv_bfloat16 h0 = __float2bfloat16(v.x);
    const __nv_bfloat16 h1 = __float2bfloat16(v.y);
    const __nv_bfloat16 h2 = __float2bfloat16(v.z);
    const __nv_bfloat16 h3 = __float2bfloat16(v.w);
    const __nv_bfloat16 l0 = __float2bfloat16(v.x - __bfloat162float(h0));
    const __nv_bfloat16 l1 = __float2bfloat16(v.y - __bfloat162float(h1));
    const __nv_bfloat16 l2 = __float2bfloat16(v.z - __bfloat162float(h2));
    const __nv_bfloat16 l3 = __float2bfloat16(v.w - __bfloat162float(h3));
    __nv_bfloat162* ph = (__nv_bfloat162*)(g_Eh + i);
    __nv_bfloat162* pl = (__nv_bfloat162*)(g_El + i);
    ph[0] = __halves2bfloat162(h0, h1);
    ph[1] = __halves2bfloat162(h2, h3);
    pl[0] = __halves2bfloat162(l0, l1);
    pl[1] = __halves2bfloat162(l2, l3);
}

// ---------------------------------------------------------------------------
// K1: w0/w1 = t0@W0 - t1@W1 + bw0 ; t0@W1 + t1@W0 + bw1
// 2 rows/block -> 512 blocks (latency-bound kernel: more CTAs > less traffic)
// ---------------------------------------------------------------------------
#define K1_ROWS 2
__global__ __launch_bounds__(256) void k1_wproj(
    const int* __restrict__ x,
    const float* __restrict__ E_ent, const float* __restrict__ E_rel,
    const float* __restrict__ W0, const float* __restrict__ W1,
    const float* __restrict__ bw0, const float* __restrict__ bw1)
{
    __shared__ float t0s[K1_ROWS][TWO_R];
    __shared__ float t1s[K1_ROWS][TWO_R];
    const int b0 = blockIdx.x * K1_ROWS;
    const int tid = threadIdx.x;

    for (int rr = 0; rr < K1_ROWS; rr++) {
        const int b = b0 + rr;
        const size_t lhs = (size_t)x[b * 3 + 0];
        const size_t rel = (size_t)x[b * 3 + 1];
        const float* lrow = E_ent + lhs * TWO_R;
        const float* rrow = E_rel + rel * TWO_R;
        for (int j = tid; j < TWO_R; j += 256) {
            if (j < RANK) {
                t0s[rr][j] = lrow[j];
                t1s[rr][j] = lrow[RANK + j];
            } else {
                t0s[rr][j] = rrow[j - RANK];
                t1s[rr][j] = rrow[RANK + (j - RANK)];
            }
        }
    }
    __syncthreads();

    const int k = tid;
    float a0[K1_ROWS], a1[K1_ROWS];
#pragma unroll
    for (int rr = 0; rr < K1_ROWS; rr++) { a0[rr] = 0.f; a1[rr] = 0.f; }

#pragma unroll 8
    for (int j = 0; j < TWO_R; j++) {
        const float w0jk = W0[j * RANK + k];
        const float w1jk = W1[j * RANK + k];
#pragma unroll
        for (int rr = 0; rr < K1_ROWS; rr++) {
            const float a = t0s[rr][j];
            const float c = t1s[rr][j];
            a0[rr] += a * w0jk - c * w1jk;
            a1[rr] += a * w1jk + c * w0jk;
        }
    }
    const float b0k = bw0[k], b1k = bw1[k];
#pragma unroll
    for (int rr = 0; rr < K1_ROWS; rr++) {
        g_w0[(b0 + rr) * RANK + k] = a0[rr] + b0k;
        g_w1[(b0 + rr) * RANK + k] = a1[rr] + b1k;
    }
}

// ---------------------------------------------------------------------------
// K2: logits over 50 neighbors, softmax, ec0/ec1 weighted sums.
// Neighbor rows staged once into dynamic smem (100 KB) via cp.async.
// ---------------------------------------------------------------------------
#define K2_SMEM (MAX_NB * TWO_R * 4)   // 102400
__global__ __launch_bounds__(256) void k2_attn(
    const int* __restrict__ nb_idx, const float* __restrict__ E_ent)
{
    extern __shared__ __align__(16) float nbs[];   // [MAX_NB][TWO_R]
    __shared__ float w0s[RANK], w1s[RANK];
    __shared__ float logit_s[MAX_NB];
    __shared__ float alpha_s[MAX_NB];
    __shared__ int   idx_s[MAX_NB];

    const int b = blockIdx.x;
    const int tid = threadIdx.x;
    const int wid = tid >> 5;
    const int lane = tid & 31;

    w0s[tid] = g_w0[b * RANK + tid];
    w1s[tid] = g_w1[b * RANK + tid];
    if (tid < MAX_NB) idx_s[tid] = nb_idx[b * MAX_NB + tid];
    __syncthreads();

    const uint32_t nbs_u = smem_to_u32(nbs);
    for (int u = tid; u < MAX_NB * 128; u += 256) {
        const int m = u >> 7;
        const int q = u & 127;
        CP_ASYNC16(nbs_u + (uint32_t)u * 16,
                   E_ent + (size_t)idx_s[m] * TWO_R + q * 4);
    }
    CP_ASYNC_COMMIT();
    CP_ASYNC_WAIT_GROUP(0);
    __syncthreads();

    for (int m = wid; m < MAX_NB; m += 8) {
        const float* row = nbs + m * TWO_R;
        float s = 0.f;
#pragma unroll
        for (int k = lane; k < RANK; k += 32)
            s += w0s[k] * row[k] - w1s[k] * row[RANK + k];
#pragma unroll
        for (int o = 16; o > 0; o >>= 1) s += __shfl_xor_sync(0xffffffffu, s, o);
        if (lane == 0) logit_s[m] = s;
    }
    __syncthreads();

    if (tid == 0) {
        float mx = logit_s[0];
        for (int m = 1; m < MAX_NB; m++) mx = fmaxf(mx, logit_s[m]);
        float sum = 0.f;
        for (int m = 0; m < MAX_NB; m++) { float e = __expf(logit_s[m] - mx); alpha_s[m] = e; sum += e; }
        const float inv = 1.0f / sum;
        for (int m = 0; m < MAX_NB; m++) alpha_s[m] *= inv;
    }
    __syncthreads();

    const int k = tid;
    float acc0 = 0.f, acc1 = 0.f;
#pragma unroll 10
    for (int m = 0; m < MAX_NB; m++) {
        const float a = alpha_s[m];
        acc0 += a * nbs[m * TWO_R + k];
        acc1 += a * nbs[m * TWO_R + RANK + k];
    }
    g_ec0[b * RANK + k] = acc0;
    g_ec1[b * RANK + k] = acc1;
}

// ---------------------------------------------------------------------------
// K3a: ec0n/ec1n complex projection by W20/W21, 2 rows/block -> 512 blocks
// ---------------------------------------------------------------------------
#define K3_ROWS 2
__global__ __launch_bounds__(256) void k3a_ecproj(
    const float* __restrict__ W20, const float* __restrict__ W21,
    const float* __restrict__ bw20, const float* __restrict__ bw21)
{
    __shared__ float e0s[K3_ROWS][RANK];
    __shared__ float e1s[K3_ROWS][RANK];
    const int b0 = blockIdx.x * K3_ROWS;
    const int tid = threadIdx.x;

    for (int rr = 0; rr < K3_ROWS; rr++) {
        e0s[rr][tid] = g_ec0[(b0 + rr) * RANK + tid];
        e1s[rr][tid] = g_ec1[(b0 + rr) * RANK + tid];
    }
    __syncthreads();

    const int k = tid;
    float a0[K3_ROWS], a1[K3_ROWS];
#pragma unroll
    for (int rr = 0; rr < K3_ROWS; rr++) { a0[rr] = 0.f; a1[rr] = 0.f; }

#pragma unroll 8
    for (int j = 0; j < RANK; j++) {
        const float w20 = W20[j * RANK + k];
        const float w21 = W21[j * RANK + k];
#pragma unroll
        for (int rr = 0; rr < K3_ROWS; rr++) {
            const float a = e0s[rr][j];
            const float c = e1s[rr][j];
            a0[rr] += a * w20 - c * w21;
            a1[rr] += a * w21 + c * w20;
        }
    }
    const float b20 = bw20[k], b21 = bw21[k];
#pragma unroll
    for (int rr = 0; rr < K3_ROWS; rr++) {
        g_en0[(b0 + rr) * RANK + k] = a0[rr] + b20;
        g_en1[(b0 + rr) * RANK + k] = a1[rr] + b21;
    }
}

// ---------------------------------------------------------------------------
// K3b: gate scalar, gec, q_re/q_im (split bf16 into g_Qh/g_Ql), norms
// ---------------------------------------------------------------------------
__global__ __launch_bounds__(256) void k3b_gate_q(
    const int* __restrict__ x,
    const float* __restrict__ E_ent, const float* __restrict__ E_rel,
    const float* __restrict__ Uo0, const float* __restrict__ Uo1,
    const float* __restrict__ Wo0, const float* __restrict__ b_g,
    float* __restrict__ out)
{
    __shared__ float warp_part[8];
    __shared__ float g_sh;
    const int b = blockIdx.x;
    const int k = threadIdx.x;
    const int wid = k >> 5, lane = k & 31;

    const size_t lhs = (size_t)x[b * 3 + 0];
    const size_t rel = (size_t)x[b * 3 + 1];
    const size_t rhs = (size_t)x[b * 3 + 2];

    const float l0 = E_ent[lhs * TWO_R + k];
    const float l1 = E_ent[lhs * TWO_R + RANK + k];
    const float r0 = E_rel[rel * TWO_R + k];
    const float r1 = E_rel[rel * TWO_R + RANK + k];
    const float o0 = E_ent[rhs * TWO_R + k];
    const float o1 = E_ent[rhs * TWO_R + RANK + k];

    const float en0 = g_en0[b * RANK + k];
    const float en1 = g_en1[b * RANK + k];

    const float sr = l0 * r0 - l1 * r1;
    const float si = l1 * r0 + l0 * r1;

    float p = sr * Uo0[k] - si * Uo1[k] + en0 * Wo0[k];
#pragma unroll
    for (int o = 16; o > 0; o >>= 1) p += __shfl_xor_sync(0xffffffffu, p, o);
    if (lane == 0) warp_part[wid] = p;
    __syncthreads();
    if (k == 0) {
        float tot = 0.f;
#pragma unroll
        for (int w = 0; w < 8; w++) tot += warp_part[w];
        tot += b_g[0];
        g_sh = 1.0f / (1.0f + __expf(-tot));
    }
    __syncthreads();
    const float g = g_sh;

    const float gec0 = g * en0 + (1.0f - g);
    const float gec1 = g * en1;

    const float q_re = sr * gec0 + si * gec1;
    const float q_im = si * gec0 - sr * gec1;

    const __nv_bfloat16 qrh = __float2bfloat16(q_re);
    const __nv_bfloat16 qih = __float2bfloat16(q_im);
    g_Qh[b * TWO_R + k]        = qrh;
    g_Qh[b * TWO_R + RANK + k] = qih;
    g_Ql[b * TWO_R + k]        = __float2bfloat16(q_re - __bfloat162float(qrh));
    g_Ql[b * TWO_R + RANK + k] = __float2bfloat16(q_im - __bfloat162float(qih));

    const size_t nk = (size_t)b * RANK + k;
    out[OFF_NLHS + nk] = sqrtf(l0 * l0 + l1 * l1);
    out[OFF_NREL + nk] = sqrtf(r0 * r0 + r1 * r1);
    out[OFF_NRHS + nk] = sqrtf(o0 * o0 + o1 * o1);
    out[OFF_NGEC + nk] = sqrtf(gec0 * gec0 + gec1 * gec1);
}

// ---------------------------------------------------------------------------
// K4: scores = Q (1024x512) @ E^T (512x100000), split-bf16 (3 products) on
// mma.sync.m16n8k16. CTA tile 128x256, 16 warps (4x4), warp tile 32x64,
// K chunk 32, 3-stage cp.async pipeline. 4 warps/SMSP hide ldsm+sync latency.
// Operand register reuse: Bl loads into Bh regs, Al into Ah regs.
// ---------------------------------------------------------------------------
#define NCHUNK 16
#define ROW_B    80                    // padded row bytes (64B data + 16B pad)
#define A_TILE_B (128 * ROW_B)         // 10240
#define B_TILE_B (256 * ROW_B)         // 20480
#define STAGE_B  (2 * A_TILE_B + 2 * B_TILE_B)   // 61440
#define NSTAGE   3
#define SMEM_K4  (NSTAGE * STAGE_B)    // 184320
#define K4_THREADS 512

__device__ __forceinline__ void k4_load_chunk(
    uint32_t sb, int chunk, int m0, int n0,
    const __nv_bfloat16* Qh, const __nv_bfloat16* Ql,
    const __nv_bfloat16* Eh, const __nv_bfloat16* El, int tid)
{
    const int k0 = chunk * 32;
    // A tiles (Ah, Al): 1024 x 16B transfers
#pragma unroll
    for (int u = 0; u < 2; u++) {
        const int idx = tid + u * K4_THREADS;   // 0..1023
        const int t   = idx >> 9;               // 0=Ah, 1=Al
        const int rem = idx & 511;
        const int row = rem >> 2;
        const int g   = rem & 3;
        const uint32_t soff = sb + (uint32_t)(t * A_TILE_B + row * ROW_B + g * 16);
        const size_t goff = (size_t)(m0 + row) * TWO_R + k0 + g * 8;
        CP_ASYNC16(soff, (t ? Ql : Qh) + goff);
    }
    // B tiles (Bh, Bl): 2048 x 16B transfers
#pragma unroll
    for (int u = 0; u < 4; u++) {
        const int idx = tid + u * K4_THREADS;   // 0..2047
        const int t   = idx >> 10;              // 0=Bh, 1=Bl
        const int rem = idx & 1023;
        const int row = rem >> 2;
        const int g   = rem & 3;
        int er = n0 + row; if (er >= N_ENT) er = N_ENT - 1;
        const uint32_t soff = sb + (uint32_t)(2 * A_TILE_B + t * B_TILE_B + row * ROW_B + g * 16);
        const size_t goff = (size_t)er * TWO_R + k0 + g * 8;
        CP_ASYNC16(soff, (t ? El : Eh) + goff);
    }
}

__global__ __launch_bounds__(K4_THREADS, 1) void k4_hmma(
    const __nv_bfloat16* __restrict__ Qh, const __nv_bfloat16* __restrict__ Ql,
    const __nv_bfloat16* __restrict__ Eh, const __nv_bfloat16* __restrict__ El,
    float* __restrict__ C)
{
    extern __shared__ __align__(1024) char smem[];
    const uint32_t sbase = smem_to_u32(smem);
    const int tid  = threadIdx.x;
    const int wid  = tid >> 5;
    const int lane = tid & 31;
    const int wm   = wid & 3;       // 0..3 -> 32-row slice
    const int wn   = wid >> 2;      // 0..3 -> 64-col slice
    const int m0   = blockIdx.x * 128;   // M fast dim: co-resident CTAs share B
    const int n0   = blockIdx.y * 256;

    const int laneRow = ((lane >> 3) & 1) * 8 + (lane & 7);
    const int laneG   = lane >> 4;
    const int rowAbase = wm * 32 + laneRow;
    const int rowBbase = wn * 64 + laneRow;

    float acc[2][8][4];
#pragma unroll
    for (int a = 0; a < 2; a++)
#pragma unroll
        for (int b = 0; b < 8; b++)
#pragma unroll
            for (int c = 0; c < 4; c++) acc[a][b][c] = 0.f;

    // prologue: fill 2 stages
    k4_load_chunk(sbase + 0 * STAGE_B, 0, m0, n0, Qh, Ql, Eh, El, tid);
    CP_ASYNC_COMMIT();
    k4_load_chunk(sbase + 1 * STAGE_B, 1, m0, n0, Qh, Ql, Eh, El, tid);
    CP_ASYNC_COMMIT();

    int stg = 0;
#pragma unroll 1
    for (int i = 0; i < NCHUNK; i++) {
        CP_ASYNC_WAIT_GROUP(1);
        __syncthreads();

        if (i + 2 < NCHUNK) {
            int ns = stg + 2; if (ns >= NSTAGE) ns -= NSTAGE;
            k4_load_chunk(sbase + ns * STAGE_B, i + 2, m0, n0, Qh, Ql, Eh, El, tid);
        }
        CP_ASYNC_COMMIT();

        const uint32_t sb  = sbase + stg * STAGE_B;
        const uint32_t sAh = sb;
        const uint32_t sAl = sb + A_TILE_B;
        const uint32_t sBh = sb + 2 * A_TILE_B;
        const uint32_t sBl = sb + 2 * A_TILE_B + B_TILE_B;

#pragma unroll
        for (int kh = 0; kh < 2; kh++) {
            const uint32_t gof = (uint32_t)((2 * kh + laneG) * 16);

            uint32_t a_op[2][4], b_op[4][4];
            // load Ah, Bh
#pragma unroll
            for (int mt = 0; mt < 2; mt++)
                ldsm_x4(a_op[mt], sAh + (uint32_t)((rowAbase + mt * 16) * ROW_B) + gof);
#pragma unroll
            for (int q = 0; q < 4; q++)
                ldsm_x4(b_op[q], sBh + (uint32_t)((rowBbase + q * 16) * ROW_B) + gof);

            // Ah * Bh
#pragma unroll
            for (int mt = 0; mt < 2; mt++)
#pragma unroll
                for (int j = 0; j < 8; j++)
                    mma_16816(acc[mt][j], a_op[mt], b_op[j >> 1][j & 1], b_op[j >> 1][2 + (j & 1)]);

            // reload B regs with Bl; Ah * Bl
#pragma unroll
            for (int q = 0; q < 4; q++)
                ldsm_x4(b_op[q], sBl + (uint32_t)((rowBbase + q * 16) * ROW_B) + gof);
#pragma unroll
            for (int mt = 0; mt < 2; mt++)
#pragma unroll
                for (int j = 0; j < 8; j++)
                    mma_16816(acc[mt][j], a_op[mt], b_op[j >> 1][j & 1], b_op[j >> 1][2 + (j & 1)]);

            // reload A regs with Al, B regs with Bh; Al * Bh
#pragma unroll
            for (int mt = 0; mt < 2; mt++)
                ldsm_x4(a_op[mt], sAl + (uint32_t)((rowAbase + mt * 16) * ROW_B) + gof);
#pragma unroll
            for (int q = 0; q < 4; q++)
                ldsm_x4(b_op[q], sBh + (uint32_t)((rowBbase + q * 16) * ROW_B) + gof);
#pragma unroll
            for (int mt = 0; mt < 2; mt++)
#pragma unroll
                for (int j = 0; j < 8; j++)
                    mma_16816(acc[mt][j], a_op[mt], b_op[j >> 1][j & 1], b_op[j >> 1][2 + (j & 1)]);
        }

        stg = stg + 1; if (stg >= NSTAGE) stg = 0;
    }

    // Epilogue: C frag (m16n8): thread t -> rows t/4, t/4+8; cols 2*(t%4)+{0,1}
    const int erow = (lane >> 2);
    const int ecol = (lane & 3) * 2;
#pragma unroll
    for (int mt = 0; mt < 2; mt++) {
        const int r1 = m0 + wm * 32 + mt * 16 + erow;
#pragma unroll
        for (int j = 0; j < 8; j++) {
            const int n = n0 + wn * 64 + j * 8 + ecol;
            if (n < N_ENT) {
                float2 v01 = make_float2(acc[mt][j][0], acc[mt][j][1]);
                float2 v23 = make_float2(acc[mt][j][2], acc[mt][j][3]);
                *(float2*)(C + (size_t)r1 * N_ENT + n) = v01;
                *(float2*)(C + (size_t)(r1 + 8) * N_ENT + n) = v23;
            }
        }
    }
}

// ---------------------------------------------------------------------------
extern "C" void kernel_launch(void* const* d_in, const int* in_sizes, int n_in,
                              void* d_out, int out_size)
{
    const int*   x      = (const int*)  d_in[0];
    const int*   nb_idx = (const int*)  d_in[1];
    const float* E_ent  = (const float*)d_in[2];
    const float* E_rel  = (const float*)d_in[3];
    const float* W0     = (const float*)d_in[4];
    const float* W1     = (const float*)d_in[5];
    const float* bw0    = (const float*)d_in[6];
    const float* bw1    = (const float*)d_in[7];
    const float* W20    = (const float*)d_in[8];
    const float* W21    = (const float*)d_in[9];
    const float* bw20   = (const float*)d_in[10];
    const float* bw21   = (const float*)d_in[11];
    const float* Uo0    = (const float*)d_in[12];
    const float* Uo1    = (const float*)d_in[13];
    const float* Wo0    = (const float*)d_in[14];
    const float* b_g    = (const float*)d_in[15];
    float* out = (float*)d_out;

    __nv_bfloat16 *Qh, *Ql, *Eh, *El;
    cudaGetSymbolAddress((void**)&Qh, g_Qh);
    cudaGetSymbolAddress((void**)&Ql, g_Ql);
    cudaGetSymbolAddress((void**)&Eh, g_Eh);
    cudaGetSymbolAddress((void**)&El, g_El);

    cudaFuncSetAttribute(k4_hmma, cudaFuncAttributeMaxDynamicSharedMemorySize, SMEM_K4);
    cudaFuncSetAttribute(k2_attn, cudaFuncAttributeMaxDynamicSharedMemorySize, K2_SMEM);

    k0_splitE<<<50000, 256>>>(E_ent);

    k1_wproj<<<BATCH / K1_ROWS, 256>>>(x, E_ent, E_rel, W0, W1, bw0, bw1);
    k2_attn <<<BATCH, 256, K2_SMEM>>>(nb_idx, E_ent);
    k3a_ecproj<<<BATCH / K3_ROWS, 256>>>(W20, W21, bw20, bw21);
    k3b_gate_q<<<BATCH, 256>>>(x, E_ent, E_rel, Uo0, Uo1, Wo0, b_g, out);

    dim3 g4(BATCH / 128, (N_ENT + 255) / 256);   // (8, 391), M fast
    k4_hmma<<<g4, K4_THREADS, SMEM_K4>>>(Qh, Ql, Eh, El, out + OFF_SCORES);
}

// round 6
// speedup vs baseline: 6.9776x; 1.9908x over previous
#include <cuda_runtime.h>
#include <cuda_bf16.h>
#include <cuda_fp16.h>
#include <cstdint>
#include <math.h>

// Problem constants
#define N_ENT 100000
#define N_REL 1000
#define RANK  256
#define TWO_R 512
#define BATCH 1024
#define MAX_NB 50

// Output layout (flattened tuple): scores, n_lhs, n_rel, n_rhs, n_gec
#define OFF_SCORES 0
#define OFF_NLHS   ((size_t)BATCH * N_ENT)
#define OFF_NREL   (OFF_NLHS + (size_t)BATCH * RANK)
#define OFF_NRHS   (OFF_NREL + (size_t)BATCH * RANK)
#define OFF_NGEC   (OFF_NRHS + (size_t)BATCH * RANK)

// Power-of-2 scaling for fp16 GEMM (exact, no extra rounding)
#define SCALE_Q 1048576.0f            // 2^20
#define SCALE_E 1024.0f               // 2^10
#define SCALE_OUT 9.313225746154785e-10f   // 2^-30

// Scratch (static device globals; no allocation allowed)
__device__ float g_w0 [BATCH * RANK];
__device__ float g_w1 [BATCH * RANK];
__device__ float g_ec0[BATCH * RANK];
__device__ float g_ec1[BATCH * RANK];
__device__ float g_en0[BATCH * RANK];
__device__ float g_en1[BATCH * RANK];

// scaled fp16 operands for the big GEMM
__device__ __half g_Qf[BATCH * TWO_R];
__device__ __half g_Ef[(size_t)N_ENT * TWO_R];

// ===========================================================================
// PTX helpers (compute_103-safe subset: cp.async / ldmatrix / mma.sync only)
// ===========================================================================
__device__ __forceinline__ uint32_t smem_to_u32(const void* smem_ptr) {
    uint32_t addr;
    asm("{ .reg .u64 tmp; cvta.to.shared.u64 tmp, %1; cvt.u32.u64 %0, tmp; }"
        : "=r"(addr) : "l"(smem_ptr));
    return addr;
}

#define CP_ASYNC16(smem_u32, gptr) \
    asm volatile("cp.async.cg.shared.global [%0], [%1], 16;" \
        :: "r"(smem_u32), "l"(gptr) : "memory")

#define CP_ASYNC_COMMIT() \
    asm volatile("cp.async.commit_group;" ::: "memory")

#define CP_ASYNC_WAIT_GROUP(n) \
    asm volatile("cp.async.wait_group %0;" :: "n"(n) : "memory")

__device__ __forceinline__ void ldsm_x4(uint32_t r[4], uint32_t addr) {
    asm volatile("ldmatrix.sync.aligned.m8n8.x4.shared.b16 {%0,%1,%2,%3}, [%4];"
        : "=r"(r[0]), "=r"(r[1]), "=r"(r[2]), "=r"(r[3]) : "r"(addr));
}

__device__ __forceinline__ void mma_16816_f16(
    float c[4], const uint32_t a[4], uint32_t b0, uint32_t b1)
{
    asm volatile(
        "mma.sync.aligned.m16n8k16.row.col.f32.f16.f16.f32 "
        "{%0,%1,%2,%3}, {%4,%5,%6,%7}, {%8,%9}, {%0,%1,%2,%3};"
        : "+f"(c[0]), "+f"(c[1]), "+f"(c[2]), "+f"(c[3])
        : "r"(a[0]), "r"(a[1]), "r"(a[2]), "r"(a[3]), "r"(b0), "r"(b1));
}

// ---------------------------------------------------------------------------
// K0: convert E_ent (fp32) into scaled fp16
// ---------------------------------------------------------------------------
__global__ __launch_bounds__(256) void k0_cvtE(const float* __restrict__ E)
{
    const size_t i = ((size_t)blockIdx.x * 256 + threadIdx.x) * 4;
    const float4 v = *(const float4*)(E + i);
    __half2* p = (__half2*)(g_Ef + i);
    p[0] = __floats2half2_rn(v.x * SCALE_E, v.y * SCALE_E);
    p[1] = __floats2half2_rn(v.z * SCALE_E, v.w * SCALE_E);
}

// ---------------------------------------------------------------------------
// K1: w0/w1 = t0@W0 - t1@W1 + bw0 ; t0@W1 + t1@W0 + bw1   (4 rows/block)
// ---------------------------------------------------------------------------
#define K1_ROWS 4
__global__ __launch_bounds__(256) void k1_wproj(
    const int* __restrict__ x,
    const float* __restrict__ E_ent, const float* __restrict__ E_rel,
    const float* __restrict__ W0, const float* __restrict__ W1,
    const float* __restrict__ bw0, const float* __restrict__ bw1)
{
    __shared__ float t0s[K1_ROWS][TWO_R];
    __shared__ float t1s[K1_ROWS][TWO_R];
    const int b0 = blockIdx.x * K1_ROWS;
    const int tid = threadIdx.x;

    for (int rr = 0; rr < K1_ROWS; rr++) {
        const int b = b0 + rr;
        const size_t lhs = (size_t)x[b * 3 + 0];
        const size_t rel = (size_t)x[b * 3 + 1];
        const float* lrow = E_ent + lhs * TWO_R;
        const float* rrow = E_rel + rel * TWO_R;
        for (int j = tid; j < TWO_R; j += 256) {
            if (j < RANK) {
                t0s[rr][j] = lrow[j];
                t1s[rr][j] = lrow[RANK + j];
            } else {
                t0s[rr][j] = rrow[j - RANK];
                t1s[rr][j] = rrow[RANK + (j - RANK)];
            }
        }
    }
    __syncthreads();

    const int k = tid;
    float a0[K1_ROWS], a1[K1_ROWS];
#pragma unroll
    for (int rr = 0; rr < K1_ROWS; rr++) { a0[rr] = 0.f; a1[rr] = 0.f; }

#pragma unroll 8
    for (int j = 0; j < TWO_R; j++) {
        const float w0jk = W0[j * RANK + k];
        const float w1jk = W1[j * RANK + k];
#pragma unroll
        for (int rr = 0; rr < K1_ROWS; rr++) {
            const float a = t0s[rr][j];
            const float c = t1s[rr][j];
            a0[rr] += a * w0jk - c * w1jk;
            a1[rr] += a * w1jk + c * w0jk;
        }
    }
    const float b0k = bw0[k], b1k = bw1[k];
#pragma unroll
    for (int rr = 0; rr < K1_ROWS; rr++) {
        g_w0[(b0 + rr) * RANK + k] = a0[rr] + b0k;
        g_w1[(b0 + rr) * RANK + k] = a1[rr] + b1k;
    }
}

// ---------------------------------------------------------------------------
// K2: logits over 50 neighbors, softmax, ec0/ec1 weighted sums.
// Neighbor rows staged once into dynamic smem (100 KB) via cp.async.
// ---------------------------------------------------------------------------
#define K2_SMEM (MAX_NB * TWO_R * 4)   // 102400
__global__ __launch_bounds__(256) void k2_attn(
    const int* __restrict__ nb_idx, const float* __restrict__ E_ent)
{
    extern __shared__ __align__(16) float nbs[];   // [MAX_NB][TWO_R]
    __shared__ float w0s[RANK], w1s[RANK];
    __shared__ float logit_s[MAX_NB];
    __shared__ float alpha_s[MAX_NB];
    __shared__ int   idx_s[MAX_NB];

    const int b = blockIdx.x;
    const int tid = threadIdx.x;
    const int wid = tid >> 5;
    const int lane = tid & 31;

    w0s[tid] = g_w0[b * RANK + tid];
    w1s[tid] = g_w1[b * RANK + tid];
    if (tid < MAX_NB) idx_s[tid] = nb_idx[b * MAX_NB + tid];
    __syncthreads();

    const uint32_t nbs_u = smem_to_u32(nbs);
    for (int u = tid; u < MAX_NB * 128; u += 256) {
        const int m = u >> 7;
        const int q = u & 127;
        CP_ASYNC16(nbs_u + (uint32_t)u * 16,
                   E_ent + (size_t)idx_s[m] * TWO_R + q * 4);
    }
    CP_ASYNC_COMMIT();
    CP_ASYNC_WAIT_GROUP(0);
    __syncthreads();

    for (int m = wid; m < MAX_NB; m += 8) {
        const float* row = nbs + m * TWO_R;
        float s = 0.f;
#pragma unroll
        for (int k = lane; k < RANK; k += 32)
            s += w0s[k] * row[k] - w1s[k] * row[RANK + k];
#pragma unroll
        for (int o = 16; o > 0; o >>= 1) s += __shfl_xor_sync(0xffffffffu, s, o);
        if (lane == 0) logit_s[m] = s;
    }
    __syncthreads();

    if (tid == 0) {
        float mx = logit_s[0];
        for (int m = 1; m < MAX_NB; m++) mx = fmaxf(mx, logit_s[m]);
        float sum = 0.f;
        for (int m = 0; m < MAX_NB; m++) { float e = __expf(logit_s[m] - mx); alpha_s[m] = e; sum += e; }
        const float inv = 1.0f / sum;
        for (int m = 0; m < MAX_NB; m++) alpha_s[m] *= inv;
    }
    __syncthreads();

    const int k = tid;
    float acc0 = 0.f, acc1 = 0.f;
#pragma unroll 10
    for (int m = 0; m < MAX_NB; m++) {
        const float a = alpha_s[m];
        acc0 += a * nbs[m * TWO_R + k];
        acc1 += a * nbs[m * TWO_R + RANK + k];
    }
    g_ec0[b * RANK + k] = acc0;
    g_ec1[b * RANK + k] = acc1;
}

// ---------------------------------------------------------------------------
// K3a: ec0n/ec1n complex projection by W20/W21, 4 rows/block
// ---------------------------------------------------------------------------
#define K3_ROWS 4
__global__ __launch_bounds__(256) void k3a_ecproj(
    const float* __restrict__ W20, const float* __restrict__ W21,
    const float* __restrict__ bw20, const float* __restrict__ bw21)
{
    __shared__ float e0s[K3_ROWS][RANK];
    __shared__ float e1s[K3_ROWS][RANK];
    const int b0 = blockIdx.x * K3_ROWS;
    const int tid = threadIdx.x;

    for (int rr = 0; rr < K3_ROWS; rr++) {
        e0s[rr][tid] = g_ec0[(b0 + rr) * RANK + tid];
        e1s[rr][tid] = g_ec1[(b0 + rr) * RANK + tid];
    }
    __syncthreads();

    const int k = tid;
    float a0[K3_ROWS], a1[K3_ROWS];
#pragma unroll
    for (int rr = 0; rr < K3_ROWS; rr++) { a0[rr] = 0.f; a1[rr] = 0.f; }

#pragma unroll 8
    for (int j = 0; j < RANK; j++) {
        const float w20 = W20[j * RANK + k];
        const float w21 = W21[j * RANK + k];
#pragma unroll
        for (int rr = 0; rr < K3_ROWS; rr++) {
            const float a = e0s[rr][j];
            const float c = e1s[rr][j];
            a0[rr] += a * w20 - c * w21;
            a1[rr] += a * w21 + c * w20;
        }
    }
    const float b20 = bw20[k], b21 = bw21[k];
#pragma unroll
    for (int rr = 0; rr < K3_ROWS; rr++) {
        g_en0[(b0 + rr) * RANK + k] = a0[rr] + b20;
        g_en1[(b0 + rr) * RANK + k] = a1[rr] + b21;
    }
}

// ---------------------------------------------------------------------------
// K3b: gate scalar, gec, q_re/q_im (scaled fp16 into g_Qf), norms
// ---------------------------------------------------------------------------
__global__ __launch_bounds__(256) void k3b_gate_q(
    const int* __restrict__ x,
    const float* __restrict__ E_ent, const float* __restrict__ E_rel,
    const float* __restrict__ Uo0, const float* __restrict__ Uo1,
    const float* __restrict__ Wo0, const float* __restrict__ b_g,
    float* __restrict__ out)
{
    __shared__ float warp_part[8];
    __shared__ float g_sh;
    const int b = blockIdx.x;
    const int k = threadIdx.x;
    const int wid = k >> 5, lane = k & 31;

    const size_t lhs = (size_t)x[b * 3 + 0];
    const size_t rel = (size_t)x[b * 3 + 1];
    const size_t rhs = (size_t)x[b * 3 + 2];

    const float l0 = E_ent[lhs * TWO_R + k];
    const float l1 = E_ent[lhs * TWO_R + RANK + k];
    const float r0 = E_rel[rel * TWO_R + k];
    const float r1 = E_rel[rel * TWO_R + RANK + k];
    const float o0 = E_ent[rhs * TWO_R + k];
    const float o1 = E_ent[rhs * TWO_R + RANK + k];

    const float en0 = g_en0[b * RANK + k];
    const float en1 = g_en1[b * RANK + k];

    const float sr = l0 * r0 - l1 * r1;
    const float si = l1 * r0 + l0 * r1;

    float p = sr * Uo0[k] - si * Uo1[k] + en0 * Wo0[k];
#pragma unroll
    for (int o = 16; o > 0; o >>= 1) p += __shfl_xor_sync(0xffffffffu, p, o);
    if (lane == 0) warp_part[wid] = p;
    __syncthreads();
    if (k == 0) {
        float tot = 0.f;
#pragma unroll
        for (int w = 0; w < 8; w++) tot += warp_part[w];
        tot += b_g[0];
        g_sh = 1.0f / (1.0f + __expf(-tot));
    }
    __syncthreads();
    const float g = g_sh;

    const float gec0 = g * en0 + (1.0f - g);
    const float gec1 = g * en1;

    const float q_re = sr * gec0 + si * gec1;
    const float q_im = si * gec0 - sr * gec1;

    g_Qf[b * TWO_R + k]        = __float2half_rn(q_re * SCALE_Q);
    g_Qf[b * TWO_R + RANK + k] = __float2half_rn(q_im * SCALE_Q);

    const size_t nk = (size_t)b * RANK + k;
    out[OFF_NLHS + nk] = sqrtf(l0 * l0 + l1 * l1);
    out[OFF_NREL + nk] = sqrtf(r0 * r0 + r1 * r1);
    out[OFF_NRHS + nk] = sqrtf(o0 * o0 + o1 * o1);
    out[OFF_NGEC + nk] = sqrtf(gec0 * gec0 + gec1 * gec1);
}

// ---------------------------------------------------------------------------
// K4: scores = Qf (1024x512) @ Ef^T (512x100000), SINGLE scaled-fp16 GEMM on
// mma.sync.m16n8k16. CTA 128x256, 8 warps (2x4), warp tile 64x64,
// K chunk 64, 3-stage cp.async. Rows padded to 144B (conflict-free ldsm).
// Epilogue rescales by 2^-30.
// ---------------------------------------------------------------------------
#define NCHUNK 8
#define ROW_B    144                   // 128B data + 16B pad
#define A_TILE_B (128 * ROW_B)         // 18432
#define B_TILE_B (256 * ROW_B)         // 36864
#define STAGE_B  (A_TILE_B + B_TILE_B) // 55296
#define NSTAGE   3
#define SMEM_K4  (NSTAGE * STAGE_B)    // 165888
#define K4_THREADS 256

__device__ __forceinline__ void k4_load_chunk(
    uint32_t sb, int chunk, int m0, int n0,
    const __half* Qf, const __half* Ef, int tid)
{
    const int k0 = chunk * 64;
    // A tile: 128 rows x 8 x 16B = 1024 transfers
#pragma unroll
    for (int u = 0; u < 4; u++) {
        const int idx = tid + u * K4_THREADS;   // 0..1023
        const int row = idx >> 3;
        const int g   = idx & 7;
        const uint32_t soff = sb + (uint32_t)(row * ROW_B + g * 16);
        CP_ASYNC16(soff, Qf + (size_t)(m0 + row) * TWO_R + k0 + g * 8);
    }
    // B tile: 256 rows x 8 x 16B = 2048 transfers
#pragma unroll
    for (int u = 0; u < 8; u++) {
        const int idx = tid + u * K4_THREADS;   // 0..2047
        const int row = idx >> 3;
        const int g   = idx & 7;
        int er = n0 + row; if (er >= N_ENT) er = N_ENT - 1;
        const uint32_t soff = sb + (uint32_t)(A_TILE_B + row * ROW_B + g * 16);
        CP_ASYNC16(soff, Ef + (size_t)er * TWO_R + k0 + g * 8);
    }
}

__global__ __launch_bounds__(K4_THREADS, 1) void k4_hmma(
    const __half* __restrict__ Qf, const __half* __restrict__ Ef,
    float* __restrict__ C)
{
    extern __shared__ __align__(1024) char smem[];
    const uint32_t sbase = smem_to_u32(smem);
    const int tid  = threadIdx.x;
    const int wid  = tid >> 5;
    const int lane = tid & 31;
    const int wm   = wid & 1;       // 0..1 -> 64-row slice
    const int wn   = wid >> 1;      // 0..3 -> 64-col slice
    const int m0   = blockIdx.x * 128;   // M fast dim: co-resident CTAs share B
    const int n0   = blockIdx.y * 256;

    const int laneRow = ((lane >> 3) & 1) * 8 + (lane & 7);
    const int laneG   = lane >> 4;
    const int rowAbase = wm * 64 + laneRow;
    const int rowBbase = wn * 64 + laneRow;

    float acc[4][8][4];
#pragma unroll
    for (int a = 0; a < 4; a++)
#pragma unroll
        for (int b = 0; b < 8; b++)
#pragma unroll
            for (int c = 0; c < 4; c++) acc[a][b][c] = 0.f;

    // prologue: fill 2 stages
    k4_load_chunk(sbase + 0 * STAGE_B, 0, m0, n0, Qf, Ef, tid);
    CP_ASYNC_COMMIT();
    k4_load_chunk(sbase + 1 * STAGE_B, 1, m0, n0, Qf, Ef, tid);
    CP_ASYNC_COMMIT();

    int stg = 0;
#pragma unroll 1
    for (int i = 0; i < NCHUNK; i++) {
        CP_ASYNC_WAIT_GROUP(1);
        __syncthreads();

        if (i + 2 < NCHUNK) {
            int ns = stg + 2; if (ns >= NSTAGE) ns -= NSTAGE;
            k4_load_chunk(sbase + ns * STAGE_B, i + 2, m0, n0, Qf, Ef, tid);
        }
        CP_ASYNC_COMMIT();

        const uint32_t sA = sbase + stg * STAGE_B;
        const uint32_t sB = sA + A_TILE_B;

#pragma unroll
        for (int kh = 0; kh < 4; kh++) {
            const uint32_t gof = (uint32_t)(kh * 32 + laneG * 16);

            uint32_t a_op[4][4], b_op[4][4];
#pragma unroll
            for (int mt = 0; mt < 4; mt++)
                ldsm_x4(a_op[mt], sA + (uint32_t)((rowAbase + mt * 16) * ROW_B) + gof);
#pragma unroll
            for (int q = 0; q < 4; q++)
                ldsm_x4(b_op[q], sB + (uint32_t)((rowBbase + q * 16) * ROW_B) + gof);

#pragma unroll
            for (int mt = 0; mt < 4; mt++)
#pragma unroll
                for (int j = 0; j < 8; j++)
                    mma_16816_f16(acc[mt][j], a_op[mt],
                                  b_op[j >> 1][j & 1], b_op[j >> 1][2 + (j & 1)]);
        }

        stg = stg + 1; if (stg >= NSTAGE) stg = 0;
    }

    // Epilogue: rescale by 2^-30 and store.
    // C frag (m16n8): thread t -> rows t/4, t/4+8; cols 2*(t%4)+{0,1}
    const int erow = (lane >> 2);
    const int ecol = (lane & 3) * 2;
#pragma unroll
    for (int mt = 0; mt < 4; mt++) {
        const int r1 = m0 + wm * 64 + mt * 16 + erow;
#pragma unroll
        for (int j = 0; j < 8; j++) {
            const int n = n0 + wn * 64 + j * 8 + ecol;
            if (n < N_ENT) {
                float2 v01 = make_float2(acc[mt][j][0] * SCALE_OUT,
                                         acc[mt][j][1] * SCALE_OUT);
                float2 v23 = make_float2(acc[mt][j][2] * SCALE_OUT,
                                         acc[mt][j][3] * SCALE_OUT);
                *(float2*)(C + (size_t)r1 * N_ENT + n) = v01;
                *(float2*)(C + (size_t)(r1 + 8) * N_ENT + n) = v23;
            }
        }
    }
}

// ---------------------------------------------------------------------------
extern "C" void kernel_launch(void* const* d_in, const int* in_sizes, int n_in,
                              void* d_out, int out_size)
{
    const int*   x      = (const int*)  d_in[0];
    const int*   nb_idx = (const int*)  d_in[1];
    const float* E_ent  = (const float*)d_in[2];
    const float* E_rel  = (const float*)d_in[3];
    const float* W0     = (const float*)d_in[4];
    const float* W1     = (const float*)d_in[5];
    const float* bw0    = (const float*)d_in[6];
    const float* bw1    = (const float*)d_in[7];
    const float* W20    = (const float*)d_in[8];
    const float* W21    = (const float*)d_in[9];
    const float* bw20   = (const float*)d_in[10];
    const float* bw21   = (const float*)d_in[11];
    const float* Uo0    = (const float*)d_in[12];
    const float* Uo1    = (const float*)d_in[13];
    const float* Wo0    = (const float*)d_in[14];
    const float* b_g    = (const float*)d_in[15];
    float* out = (float*)d_out;

    __half *Qf, *Ef;
    cudaGetSymbolAddress((void**)&Qf, g_Qf);
    cudaGetSymbolAddress((void**)&Ef, g_Ef);

    cudaFuncSetAttribute(k4_hmma, cudaFuncAttributeMaxDynamicSharedMemorySize, SMEM_K4);
    cudaFuncSetAttribute(k2_attn, cudaFuncAttributeMaxDynamicSharedMemorySize, K2_SMEM);

    k0_cvtE<<<50000, 256>>>(E_ent);

    k1_wproj<<<BATCH / K1_ROWS, 256>>>(x, E_ent, E_rel, W0, W1, bw0, bw1);
    k2_attn <<<BATCH, 256, K2_SMEM>>>(nb_idx, E_ent);
    k3a_ecproj<<<BATCH / K3_ROWS, 256>>>(W20, W21, bw20, bw21);
    k3b_gate_q<<<BATCH, 256>>>(x, E_ent, E_rel, Uo0, Uo1, Wo0, b_g, out);

    dim3 g4(BATCH / 128, (N_ENT + 255) / 256);   // (8, 391), M fast
    k4_hmma<<<g4, K4_THREADS, SMEM_K4>>>(Qf, Ef, out + OFF_SCORES);
}

// round 8
// speedup vs baseline: 7.1216x; 1.0206x over previous
#include <cuda_runtime.h>
#include <cuda_bf16.h>
#include <cuda_fp16.h>
#include <cstdint>
#include <math.h>

// Problem constants
#define N_ENT 100000
#define N_REL 1000
#define RANK  256
#define TWO_R 512
#define BATCH 1024
#define MAX_NB 50

// Output layout (flattened tuple): scores, n_lhs, n_rel, n_rhs, n_gec
#define OFF_SCORES 0
#define OFF_NLHS   ((size_t)BATCH * N_ENT)
#define OFF_NREL   (OFF_NLHS + (size_t)BATCH * RANK)
#define OFF_NRHS   (OFF_NREL + (size_t)BATCH * RANK)
#define OFF_NGEC   (OFF_NRHS + (size_t)BATCH * RANK)

// Power-of-2 scaling for fp16 GEMM (exact, no extra rounding)
#define SCALE_Q 1048576.0f            // 2^20
#define SCALE_E 1024.0f               // 2^10
#define SCALE_OUT 9.313225746154785e-10f   // 2^-30

// Scratch (static device globals; no allocation allowed)
__device__ float g_w0 [BATCH * RANK];
__device__ float g_w1 [BATCH * RANK];
__device__ float g_ec0[BATCH * RANK];
__device__ float g_ec1[BATCH * RANK];
__device__ float g_en0[BATCH * RANK];
__device__ float g_en1[BATCH * RANK];

// scaled fp16 operands for the big GEMM
__device__ __half g_Qf[BATCH * TWO_R];
__device__ __half g_Ef[(size_t)N_ENT * TWO_R];

// ===========================================================================
// PTX helpers (compute_103-safe subset: cp.async / ldmatrix / mma.sync only)
// ===========================================================================
__device__ __forceinline__ uint32_t smem_to_u32(const void* smem_ptr) {
    uint32_t addr;
    asm("{ .reg .u64 tmp; cvta.to.shared.u64 tmp, %1; cvt.u32.u64 %0, tmp; }"
        : "=r"(addr) : "l"(smem_ptr));
    return addr;
}

#define CP_ASYNC16(smem_u32, gptr) \
    asm volatile("cp.async.cg.shared.global [%0], [%1], 16;" \
        :: "r"(smem_u32), "l"(gptr) : "memory")

#define CP_ASYNC_COMMIT() \
    asm volatile("cp.async.commit_group;" ::: "memory")

#define CP_ASYNC_WAIT_GROUP(n) \
    asm volatile("cp.async.wait_group %0;" :: "n"(n) : "memory")

__device__ __forceinline__ void ldsm_x4(uint32_t r[4], uint32_t addr) {
    asm volatile("ldmatrix.sync.aligned.m8n8.x4.shared.b16 {%0,%1,%2,%3}, [%4];"
        : "=r"(r[0]), "=r"(r[1]), "=r"(r[2]), "=r"(r[3]) : "r"(addr));
}

__device__ __forceinline__ void mma_16816_f16(
    float c[4], const uint32_t a[4], uint32_t b0, uint32_t b1)
{
    asm volatile(
        "mma.sync.aligned.m16n8k16.row.col.f32.f16.f16.f32 "
        "{%0,%1,%2,%3}, {%4,%5,%6,%7}, {%8,%9}, {%0,%1,%2,%3};"
        : "+f"(c[0]), "+f"(c[1]), "+f"(c[2]), "+f"(c[3])
        : "r"(a[0]), "r"(a[1]), "r"(a[2]), "r"(a[3]), "r"(b0), "r"(b1));
}

// ---------------------------------------------------------------------------
// K0: convert E_ent (fp32) into scaled fp16
// ---------------------------------------------------------------------------
__global__ __launch_bounds__(256) void k0_cvtE(const float* __restrict__ E)
{
    const size_t i = ((size_t)blockIdx.x * 256 + threadIdx.x) * 4;
    const float4 v = *(const float4*)(E + i);
    __half2* p = (__half2*)(g_Ef + i);
    p[0] = __floats2half2_rn(v.x * SCALE_E, v.y * SCALE_E);
    p[1] = __floats2half2_rn(v.z * SCALE_E, v.w * SCALE_E);
}

// ---------------------------------------------------------------------------
// K1: w0/w1 = t0@W0 - t1@W1 + bw0 ; t0@W1 + t1@W0 + bw1   (4 rows/block)
// ---------------------------------------------------------------------------
#define K1_ROWS 4
__global__ __launch_bounds__(256) void k1_wproj(
    const int* __restrict__ x,
    const float* __restrict__ E_ent, const float* __restrict__ E_rel,
    const float* __restrict__ W0, const float* __restrict__ W1,
    const float* __restrict__ bw0, const float* __restrict__ bw1)
{
    __shared__ float t0s[K1_ROWS][TWO_R];
    __shared__ float t1s[K1_ROWS][TWO_R];
    const int b0 = blockIdx.x * K1_ROWS;
    const int tid = threadIdx.x;

    for (int rr = 0; rr < K1_ROWS; rr++) {
        const int b = b0 + rr;
        const size_t lhs = (size_t)x[b * 3 + 0];
        const size_t rel = (size_t)x[b * 3 + 1];
        const float* lrow = E_ent + lhs * TWO_R;
        const float* rrow = E_rel + rel * TWO_R;
        for (int j = tid; j < TWO_R; j += 256) {
            if (j < RANK) {
                t0s[rr][j] = lrow[j];
                t1s[rr][j] = lrow[RANK + j];
            } else {
                t0s[rr][j] = rrow[j - RANK];
                t1s[rr][j] = rrow[RANK + (j - RANK)];
            }
        }
    }
    __syncthreads();

    const int k = tid;
    float a0[K1_ROWS], a1[K1_ROWS];
#pragma unroll
    for (int rr = 0; rr < K1_ROWS; rr++) { a0[rr] = 0.f; a1[rr] = 0.f; }

#pragma unroll 8
    for (int j = 0; j < TWO_R; j++) {
        const float w0jk = W0[j * RANK + k];
        const float w1jk = W1[j * RANK + k];
#pragma unroll
        for (int rr = 0; rr < K1_ROWS; rr++) {
            const float a = t0s[rr][j];
            const float c = t1s[rr][j];
            a0[rr] += a * w0jk - c * w1jk;
            a1[rr] += a * w1jk + c * w0jk;
        }
    }
    const float b0k = bw0[k], b1k = bw1[k];
#pragma unroll
    for (int rr = 0; rr < K1_ROWS; rr++) {
        g_w0[(b0 + rr) * RANK + k] = a0[rr] + b0k;
        g_w1[(b0 + rr) * RANK + k] = a1[rr] + b1k;
    }
}

// ---------------------------------------------------------------------------
// K2: logits over 50 neighbors, softmax, ec0/ec1 weighted sums.
// Neighbor rows staged once into dynamic smem (100 KB) via cp.async.
// ---------------------------------------------------------------------------
#define K2_SMEM (MAX_NB * TWO_R * 4)   // 102400
__global__ __launch_bounds__(256) void k2_attn(
    const int* __restrict__ nb_idx, const float* __restrict__ E_ent)
{
    extern __shared__ __align__(16) float nbs[];   // [MAX_NB][TWO_R]
    __shared__ float w0s[RANK], w1s[RANK];
    __shared__ float logit_s[MAX_NB];
    __shared__ float alpha_s[MAX_NB];
    __shared__ int   idx_s[MAX_NB];

    const int b = blockIdx.x;
    const int tid = threadIdx.x;
    const int wid = tid >> 5;
    const int lane = tid & 31;

    w0s[tid] = g_w0[b * RANK + tid];
    w1s[tid] = g_w1[b * RANK + tid];
    if (tid < MAX_NB) idx_s[tid] = nb_idx[b * MAX_NB + tid];
    __syncthreads();

    const uint32_t nbs_u = smem_to_u32(nbs);
    for (int u = tid; u < MAX_NB * 128; u += 256) {
        const int m = u >> 7;
        const int q = u & 127;
        CP_ASYNC16(nbs_u + (uint32_t)u * 16,
                   E_ent + (size_t)idx_s[m] * TWO_R + q * 4);
    }
    CP_ASYNC_COMMIT();
    CP_ASYNC_WAIT_GROUP(0);
    __syncthreads();

    for (int m = wid; m < MAX_NB; m += 8) {
        const float* row = nbs + m * TWO_R;
        float s = 0.f;
#pragma unroll
        for (int k = lane; k < RANK; k += 32)
            s += w0s[k] * row[k] - w1s[k] * row[RANK + k];
#pragma unroll
        for (int o = 16; o > 0; o >>= 1) s += __shfl_xor_sync(0xffffffffu, s, o);
        if (lane == 0) logit_s[m] = s;
    }
    __syncthreads();

    if (tid == 0) {
        float mx = logit_s[0];
        for (int m = 1; m < MAX_NB; m++) mx = fmaxf(mx, logit_s[m]);
        float sum = 0.f;
        for (int m = 0; m < MAX_NB; m++) { float e = __expf(logit_s[m] - mx); alpha_s[m] = e; sum += e; }
        const float inv = 1.0f / sum;
        for (int m = 0; m < MAX_NB; m++) alpha_s[m] *= inv;
    }
    __syncthreads();

    const int k = tid;
    float acc0 = 0.f, acc1 = 0.f;
#pragma unroll 10
    for (int m = 0; m < MAX_NB; m++) {
        const float a = alpha_s[m];
        acc0 += a * nbs[m * TWO_R + k];
        acc1 += a * nbs[m * TWO_R + RANK + k];
    }
    g_ec0[b * RANK + k] = acc0;
    g_ec1[b * RANK + k] = acc1;
}

// ---------------------------------------------------------------------------
// K3a: ec0n/ec1n complex projection by W20/W21, 4 rows/block
// ---------------------------------------------------------------------------
#define K3_ROWS 4
__global__ __launch_bounds__(256) void k3a_ecproj(
    const float* __restrict__ W20, const float* __restrict__ W21,
    const float* __restrict__ bw20, const float* __restrict__ bw21)
{
    __shared__ float e0s[K3_ROWS][RANK];
    __shared__ float e1s[K3_ROWS][RANK];
    const int b0 = blockIdx.x * K3_ROWS;
    const int tid = threadIdx.x;

    for (int rr = 0; rr < K3_ROWS; rr++) {
        e0s[rr][tid] = g_ec0[(b0 + rr) * RANK + tid];
        e1s[rr][tid] = g_ec1[(b0 + rr) * RANK + tid];
    }
    __syncthreads();

    const int k = tid;
    float a0[K3_ROWS], a1[K3_ROWS];
#pragma unroll
    for (int rr = 0; rr < K3_ROWS; rr++) { a0[rr] = 0.f; a1[rr] = 0.f; }

#pragma unroll 8
    for (int j = 0; j < RANK; j++) {
        const float w20 = W20[j * RANK + k];
        const float w21 = W21[j * RANK + k];
#pragma unroll
        for (int rr = 0; rr < K3_ROWS; rr++) {
            const float a = e0s[rr][j];
            const float c = e1s[rr][j];
            a0[rr] += a * w20 - c * w21;
            a1[rr] += a * w21 + c * w20;
        }
    }
    const float b20 = bw20[k], b21 = bw21[k];
#pragma unroll
    for (int rr = 0; rr < K3_ROWS; rr++) {
        g_en0[(b0 + rr) * RANK + k] = a0[rr] + b20;
        g_en1[(b0 + rr) * RANK + k] = a1[rr] + b21;
    }
}

// ---------------------------------------------------------------------------
// K3b: gate scalar, gec, q_re/q_im (scaled fp16 into g_Qf), norms
// ---------------------------------------------------------------------------
__global__ __launch_bounds__(256) void k3b_gate_q(
    const int* __restrict__ x,
    const float* __restrict__ E_ent, const float* __restrict__ E_rel,
    const float* __restrict__ Uo0, const float* __restrict__ Uo1,
    const float* __restrict__ Wo0, const float* __restrict__ b_g,
    float* __restrict__ out)
{
    __shared__ float warp_part[8];
    __shared__ float g_sh;
    const int b = blockIdx.x;
    const int k = threadIdx.x;
    const int wid = k >> 5, lane = k & 31;

    const size_t lhs = (size_t)x[b * 3 + 0];
    const size_t rel = (size_t)x[b * 3 + 1];
    const size_t rhs = (size_t)x[b * 3 + 2];

    const float l0 = E_ent[lhs * TWO_R + k];
    const float l1 = E_ent[lhs * TWO_R + RANK + k];
    const float r0 = E_rel[rel * TWO_R + k];
    const float r1 = E_rel[rel * TWO_R + RANK + k];
    const float o0 = E_ent[rhs * TWO_R + k];
    const float o1 = E_ent[rhs * TWO_R + RANK + k];

    const float en0 = g_en0[b * RANK + k];
    const float en1 = g_en1[b * RANK + k];

    const float sr = l0 * r0 - l1 * r1;
    const float si = l1 * r0 + l0 * r1;

    float p = sr * Uo0[k] - si * Uo1[k] + en0 * Wo0[k];
#pragma unroll
    for (int o = 16; o > 0; o >>= 1) p += __shfl_xor_sync(0xffffffffu, p, o);
    if (lane == 0) warp_part[wid] = p;
    __syncthreads();
    if (k == 0) {
        float tot = 0.f;
#pragma unroll
        for (int w = 0; w < 8; w++) tot += warp_part[w];
        tot += b_g[0];
        g_sh = 1.0f / (1.0f + __expf(-tot));
    }
    __syncthreads();
    const float g = g_sh;

    const float gec0 = g * en0 + (1.0f - g);
    const float gec1 = g * en1;

    const float q_re = sr * gec0 + si * gec1;
    const float q_im = si * gec0 - sr * gec1;

    g_Qf[b * TWO_R + k]        = __float2half_rn(q_re * SCALE_Q);
    g_Qf[b * TWO_R + RANK + k] = __float2half_rn(q_im * SCALE_Q);

    const size_t nk = (size_t)b * RANK + k;
    out[OFF_NLHS + nk] = sqrtf(l0 * l0 + l1 * l1);
    out[OFF_NREL + nk] = sqrtf(r0 * r0 + r1 * r1);
    out[OFF_NRHS + nk] = sqrtf(o0 * o0 + o1 * o1);
    out[OFF_NGEC + nk] = sqrtf(gec0 * gec0 + gec1 * gec1);
}

// ---------------------------------------------------------------------------
// K4: scores = Qf (1024x512) @ Ef^T (512x100000), single scaled-fp16 GEMM on
// mma.sync.m16n8k16. PERSISTENT CTAs: grid = #SMs, each CTA walks a static
// tile list (tile = 128x256, M fast so co-resident CTAs share B in L2).
// The cp.async chunk stream is CONTINUOUS across tiles (stage = pos % 3):
// no per-tile prologue stall, epilogue overlaps next tile's loads.
// ---------------------------------------------------------------------------
#define NCHUNK 8
#define NTILE_M (BATCH / 128)                 // 8
#define NTILE_N ((N_ENT + 255) / 256)         // 391
#define NTILES  (NTILE_M * NTILE_N)           // 3128
#define ROW_B    144                   // 128B data + 16B pad
#define A_TILE_B (128 * ROW_B)         // 18432
#define B_TILE_B (256 * ROW_B)         // 36864
#define STAGE_B  (A_TILE_B + B_TILE_B) // 55296
#define NSTAGE   3
#define SMEM_K4  (NSTAGE * STAGE_B)    // 165888
#define K4_THREADS 256

// Issue loads for global stream position p (tile = own-tile p>>3, chunk p&7)
__device__ __forceinline__ void k4_load_pos(
    uint32_t sbase, int p, int stg, int bidx, int gridx,
    const __half* Qf, const __half* Ef, int tid)
{
    const int T = bidx + (p >> 3) * gridx;
    const int chunk = p & 7;
    const int m0 = (T & (NTILE_M - 1)) * 128;
    const int n0 = (T / NTILE_M) * 256;
    const int k0 = chunk * 64;
    const uint32_t sb = sbase + (uint32_t)stg * STAGE_B;
    // A tile: 128 rows x 8 x 16B = 1024 transfers
#pragma unroll
    for (int u = 0; u < 4; u++) {
        const int idx = tid + u * K4_THREADS;   // 0..1023
        const int row = idx >> 3;
        const int g   = idx & 7;
        const uint32_t soff = sb + (uint32_t)(row * ROW_B + g * 16);
        CP_ASYNC16(soff, Qf + (size_t)(m0 + row) * TWO_R + k0 + g * 8);
    }
    // B tile: 256 rows x 8 x 16B = 2048 transfers
#pragma unroll
    for (int u = 0; u < 8; u++) {
        const int idx = tid + u * K4_THREADS;   // 0..2047
        const int row = idx >> 3;
        const int g   = idx & 7;
        int er = n0 + row; if (er >= N_ENT) er = N_ENT - 1;
        const uint32_t soff = sb + (uint32_t)(A_TILE_B + row * ROW_B + g * 16);
        CP_ASYNC16(soff, Ef + (size_t)er * TWO_R + k0 + g * 8);
    }
}

__global__ __launch_bounds__(K4_THREADS, 1) void k4_hmma(
    const __half* __restrict__ Qf, const __half* __restrict__ Ef,
    float* __restrict__ C)
{
    extern __shared__ __align__(1024) char smem[];
    const uint32_t sbase = smem_to_u32(smem);
    const int tid  = threadIdx.x;
    const int wid  = tid >> 5;
    const int lane = tid & 31;
    const int wm   = wid & 1;       // 0..1 -> 64-row slice
    const int wn   = wid >> 1;      // 0..3 -> 64-col slice
    const int bidx = blockIdx.x;
    const int gridx = gridDim.x;

    const int ntiles_own = (NTILES - bidx + gridx - 1) / gridx;
    const int pmax = ntiles_own * NCHUNK;

    const int laneRow = ((lane >> 3) & 1) * 8 + (lane & 7);
    const int laneG   = lane >> 4;
    const int rowAbase = wm * 64 + laneRow;
    const int rowBbase = wn * 64 + laneRow;

    // preload stream positions 0 and 1
    k4_load_pos(sbase, 0, 0, bidx, gridx, Qf, Ef, tid);
    CP_ASYNC_COMMIT();
    if (pmax > 1) k4_load_pos(sbase, 1, 1, bidx, gridx, Qf, Ef, tid);
    CP_ASYNC_COMMIT();

    int p_load = 2;
    int stg_load = 2;
    int stg = 0;

#pragma unroll 1
    for (int j = 0; j < ntiles_own; j++) {
        const int T = bidx + j * gridx;
        const int m0 = (T & (NTILE_M - 1)) * 128;
        const int n0 = (T / NTILE_M) * 256;

        float acc[4][8][4];
#pragma unroll
        for (int a = 0; a < 4; a++)
#pragma unroll
            for (int b = 0; b < 8; b++)
#pragma unroll
                for (int c = 0; c < 4; c++) acc[a][b][c] = 0.f;

#pragma unroll 1
        for (int i = 0; i < NCHUNK; i++) {
            CP_ASYNC_WAIT_GROUP(1);
            __syncthreads();

            if (p_load < pmax)
                k4_load_pos(sbase, p_load, stg_load, bidx, gridx, Qf, Ef, tid);
            CP_ASYNC_COMMIT();
            p_load++;
            stg_load = stg_load + 1; if (stg_load >= NSTAGE) stg_load = 0;

            const uint32_t sA = sbase + (uint32_t)stg * STAGE_B;
            const uint32_t sB = sA + A_TILE_B;

#pragma unroll
            for (int kh = 0; kh < 4; kh++) {
                const uint32_t gof = (uint32_t)(kh * 32 + laneG * 16);

                uint32_t a_op[4][4], b_op[4][4];
#pragma unroll
                for (int mt = 0; mt < 4; mt++)
                    ldsm_x4(a_op[mt], sA + (uint32_t)((rowAbase + mt * 16) * ROW_B) + gof);
#pragma unroll
                for (int q = 0; q < 4; q++)
                    ldsm_x4(b_op[q], sB + (uint32_t)((rowBbase + q * 16) * ROW_B) + gof);

#pragma unroll
                for (int mt = 0; mt < 4; mt++)
#pragma unroll
                    for (int jj = 0; jj < 8; jj++)
                        mma_16816_f16(acc[mt][jj], a_op[mt],
                                      b_op[jj >> 1][jj & 1], b_op[jj >> 1][2 + (jj & 1)]);
            }

            stg = stg + 1; if (stg >= NSTAGE) stg = 0;
        }

        // Epilogue (overlaps with next tile's in-flight cp.async loads):
        // C frag (m16n8): thread t -> rows t/4, t/4+8; cols 2*(t%4)+{0,1}
        const int erow = (lane >> 2);
        const int ecol = (lane & 3) * 2;
#pragma unroll
        for (int mt = 0; mt < 4; mt++) {
            const int r1 = m0 + wm * 64 + mt * 16 + erow;
#pragma unroll
            for (int jj = 0; jj < 8; jj++) {
                const int n = n0 + wn * 64 + jj * 8 + ecol;
                if (n < N_ENT) {
                    float2 v01 = make_float2(acc[mt][jj][0] * SCALE_OUT,
                                             acc[mt][jj][1] * SCALE_OUT);
                    float2 v23 = make_float2(acc[mt][jj][2] * SCALE_OUT,
                                             acc[mt][jj][3] * SCALE_OUT);
                    *(float2*)(C + (size_t)r1 * N_ENT + n) = v01;
                    *(float2*)(C + (size_t)(r1 + 8) * N_ENT + n) = v23;
                }
            }
        }
    }
}

// ---------------------------------------------------------------------------
extern "C" void kernel_launch(void* const* d_in, const int* in_sizes, int n_in,
                              void* d_out, int out_size)
{
    const int*   x      = (const int*)  d_in[0];
    const int*   nb_idx = (const int*)  d_in[1];
    const float* E_ent  = (const float*)d_in[2];
    const float* E_rel  = (const float*)d_in[3];
    const float* W0     = (const float*)d_in[4];
    const float* W1     = (const float*)d_in[5];
    const float* bw0    = (const float*)d_in[6];
    const float* bw1    = (const float*)d_in[7];
    const float* W20    = (const float*)d_in[8];
    const float* W21    = (const float*)d_in[9];
    const float* bw20   = (const float*)d_in[10];
    const float* bw21   = (const float*)d_in[11];
    const float* Uo0    = (const float*)d_in[12];
    const float* Uo1    = (const float*)d_in[13];
    const float* Wo0    = (const float*)d_in[14];
    const float* b_g    = (const float*)d_in[15];
    float* out = (float*)d_out;

    __half *Qf, *Ef;
    cudaGetSymbolAddress((void**)&Qf, g_Qf);
    cudaGetSymbolAddress((void**)&Ef, g_Ef);

    cudaFuncSetAttribute(k4_hmma, cudaFuncAttributeMaxDynamicSharedMemorySize, SMEM_K4);
    cudaFuncSetAttribute(k2_attn, cudaFuncAttributeMaxDynamicSharedMemorySize, K2_SMEM);

    int nsm = 148;
    cudaDeviceGetAttribute(&nsm, cudaDevAttrMultiProcessorCount, 0);

    k0_cvtE<<<50000, 256>>>(E_ent);

    k1_wproj<<<BATCH / K1_ROWS, 256>>>(x, E_ent, E_rel, W0, W1, bw0, bw1);
    k2_attn <<<BATCH, 256, K2_SMEM>>>(nb_idx, E_ent);
    k3a_ecproj<<<BATCH / K3_ROWS, 256>>>(W20, W21, bw20, bw21);
    k3b_gate_q<<<BATCH, 256>>>(x, E_ent, E_rel, Uo0, Uo1, Wo0, b_g, out);

    k4_hmma<<<nsm, K4_THREADS, SMEM_K4>>>(Qf, Ef, out + OFF_SCORES);
}